// round 7
// baseline (speedup 1.0000x reference)
#include <cuda_runtime.h>
#include <cstdint>

#define NN 50000
#define EIN 128
#define C1T 256   // H1*C1
#define C2T 128   // H2*C2

// ---------------- scratch (device globals; allocation is forbidden) ----------
// NOTE: these are ONLY touched through pointers obtained via
// cudaGetSymbolAddress in kernel_launch. Never reference them from host
// expressions (host shadow address + GB300 ATS = silent wrong memory).
__device__ float g_h1 [NN * C1T];   // x @ W1 (pre-activation, used for messages)
__device__ float g_as1[NN * 4];
__device__ float g_ad1[NN * 4];
__device__ float g_den1[NN * 4];
__device__ float g_acc1[NN * C1T];
__device__ float g_hact[NN * C1T]; // relu(norm + bias) -> layer2 input
__device__ float g_h2 [NN * C2T];
__device__ float g_as2[NN];
__device__ float g_ad2[NN];
__device__ float g_den2[NN];

// ---------------- helpers ----------------------------------------------------
__device__ __forceinline__ void red_add_v4(float* addr, float4 v) {
    asm volatile("red.global.add.v4.f32 [%0], {%1, %2, %3, %4};"
                 :: "l"(addr), "f"(v.x), "f"(v.y), "f"(v.z), "f"(v.w)
                 : "memory");
}

// ---------------- zero init --------------------------------------------------
__global__ void zero_all(float* __restrict__ acc1, float* __restrict__ den1,
                         float* __restrict__ den2, float* __restrict__ out, int N) {
    int i = blockIdx.x * blockDim.x + threadIdx.x;
    if (i < N * C1T) acc1[i] = 0.f;
    if (i < N * 4)   den1[i] = 0.f;
    if (i < N)       den2[i] = 0.f;
    if (i < N * C2T) out[i]  = 0.f;
}

// ---------------- fp32 tiled GEMM: C[M,Ncols] = A[M,K] @ B[K,Ncols] ----------
// 64x64 block tile, 256 threads, 4x4 per thread, K-step 16.
template <int K>
__global__ __launch_bounds__(256)
void gemm_kernel(const float* __restrict__ A, const float* __restrict__ B,
                 float* __restrict__ C, int M, int Ncols) {
    __shared__ float As[16][64];   // [k][row]
    __shared__ float Bs[16][64];   // [k][col]
    int tid = threadIdx.x;
    int tx = tid & 15, ty = tid >> 4;
    int row0 = blockIdx.y * 64;
    int col0 = blockIdx.x * 64;

    int ar = tid >> 2;            // 0..63 : A row within tile
    int ak = (tid & 3) * 4;       // 0,4,8,12 : k offset
    int bk = tid >> 4;            // 0..15 : B k row
    int bc = (tid & 15) * 4;      // col offset

    float acc[4][4];
    #pragma unroll
    for (int i = 0; i < 4; i++)
        #pragma unroll
        for (int j = 0; j < 4; j++) acc[i][j] = 0.f;

    for (int k0 = 0; k0 < K; k0 += 16) {
        float4 av = make_float4(0.f, 0.f, 0.f, 0.f);
        int arow = row0 + ar;
        if (arow < M)
            av = *reinterpret_cast<const float4*>(A + (size_t)arow * K + k0 + ak);
        As[ak + 0][ar] = av.x; As[ak + 1][ar] = av.y;
        As[ak + 2][ar] = av.z; As[ak + 3][ar] = av.w;

        float4 bv = *reinterpret_cast<const float4*>(
            B + (size_t)(k0 + bk) * Ncols + col0 + bc);
        *reinterpret_cast<float4*>(&Bs[bk][bc]) = bv;
        __syncthreads();

        #pragma unroll
        for (int k = 0; k < 16; k++) {
            float4 a4 = *reinterpret_cast<const float4*>(&As[k][ty * 4]);
            float4 b4 = *reinterpret_cast<const float4*>(&Bs[k][tx * 4]);
            float a[4] = {a4.x, a4.y, a4.z, a4.w};
            float b[4] = {b4.x, b4.y, b4.z, b4.w};
            #pragma unroll
            for (int i = 0; i < 4; i++)
                #pragma unroll
                for (int j = 0; j < 4; j++)
                    acc[i][j] += a[i] * b[j];
        }
        __syncthreads();
    }

    #pragma unroll
    for (int i = 0; i < 4; i++) {
        int r = row0 + ty * 4 + i;
        if (r < M) {
            float4 o = make_float4(acc[i][0], acc[i][1], acc[i][2], acc[i][3]);
            *reinterpret_cast<float4*>(C + (size_t)r * Ncols + col0 + tx * 4) = o;
        }
    }
}

// ---------------- attention coefficients: a_s/a_d per (node, head) ----------
__global__ void att_dot(const float* __restrict__ h,
                        const float* __restrict__ atts,
                        const float* __restrict__ attd,
                        float* __restrict__ as_, float* __restrict__ ad_,
                        int N, int H, int C) {
    int i = blockIdx.x * blockDim.x + threadIdx.x;
    if (i >= N * H) return;
    int hh = i % H;
    const float* hp = h + (size_t)i * C;
    const float* sp = atts + hh * C;
    const float* dp = attd + hh * C;
    float s = 0.f, d = 0.f;
    for (int c = 0; c < C; c += 4) {
        float4 v = *reinterpret_cast<const float4*>(hp + c);
        float4 a = *reinterpret_cast<const float4*>(sp + c);
        float4 b = *reinterpret_cast<const float4*>(dp + c);
        s += v.x * a.x + v.y * a.y + v.z * a.z + v.w * a.w;
        d += v.x * b.x + v.y * b.y + v.z * b.z + v.w * b.w;
    }
    as_[i] = s;
    ad_[i] = d;
}

// ---------------- layer1 edge pass: warp per edge, 4 heads x 64 ch ----------
__global__ __launch_bounds__(256)
void edge1_kernel(const int* __restrict__ ei,
                  const float* __restrict__ as1, const float* __restrict__ ad1,
                  float* __restrict__ den1,
                  const float* __restrict__ h1, float* __restrict__ acc1,
                  int E, int N) {
    int gw = (blockIdx.x * blockDim.x + threadIdx.x) >> 5;
    int lane = threadIdx.x & 31;
    int tot = E + N;
    if (gw >= tot) return;
    int src, dst;
    if (gw < E) { src = ei[gw]; dst = ei[E + gw]; }
    else        { src = dst = gw - E; }

    float w = 0.f;
    if (lane < 4) {
        float e = as1[src * 4 + lane] + ad1[dst * 4 + lane];
        e = (e > 0.f) ? e : 0.2f * e;
        w = expf(e);                       // softmax is shift-invariant: skip max
        atomicAdd(&den1[dst * 4 + lane], w);
    }
    // channel block [lane*8, lane*8+8) belongs to head lane>>3
    float wh = __shfl_sync(0xffffffffu, w, lane >> 3);

    const float4* hs = reinterpret_cast<const float4*>(h1 + (size_t)src * C1T) + lane * 2;
    float4 v0 = hs[0], v1 = hs[1];
    float* ap = acc1 + (size_t)dst * C1T + lane * 8;
    red_add_v4(ap,     make_float4(v0.x * wh, v0.y * wh, v0.z * wh, v0.w * wh));
    red_add_v4(ap + 4, make_float4(v1.x * wh, v1.y * wh, v1.z * wh, v1.w * wh));
}

// ---------------- layer2 edge pass: warp per edge, 1 head x 128 ch ----------
__global__ __launch_bounds__(256)
void edge2_kernel(const int* __restrict__ ei,
                  const float* __restrict__ as2, const float* __restrict__ ad2,
                  float* __restrict__ den2,
                  const float* __restrict__ h2, float* __restrict__ out,
                  int E, int N) {
    int gw = (blockIdx.x * blockDim.x + threadIdx.x) >> 5;
    int lane = threadIdx.x & 31;
    int tot = E + N;
    if (gw >= tot) return;
    int src, dst;
    if (gw < E) { src = ei[gw]; dst = ei[E + gw]; }
    else        { src = dst = gw - E; }

    float w = 0.f;
    if (lane == 0) {
        float e = as2[src] + ad2[dst];
        e = (e > 0.f) ? e : 0.2f * e;
        w = expf(e);
        atomicAdd(&den2[dst], w);
    }
    w = __shfl_sync(0xffffffffu, w, 0);

    float4 v = reinterpret_cast<const float4*>(h2 + (size_t)src * C2T)[lane];
    red_add_v4(out + (size_t)dst * C2T + lane * 4,
               make_float4(v.x * w, v.y * w, v.z * w, v.w * w));
}

// ---------------- finish layer1: normalize + bias + relu --------------------
__global__ void finish1(const float* __restrict__ acc1, const float* __restrict__ den1,
                        const float* __restrict__ b1, float* __restrict__ hact, int N) {
    int i = blockIdx.x * blockDim.x + threadIdx.x;
    if (i >= N * C1T) return;
    int n = i >> 8, c = i & 255, h = c >> 6;
    float v = acc1[i] / (den1[n * 4 + h] + 1e-16f) + b1[c];
    hact[i] = fmaxf(v, 0.f);
}

// ---------------- finish layer2: normalize + bias + relu (in place) ---------
__global__ void finish2(float* __restrict__ out, const float* __restrict__ den2,
                        const float* __restrict__ b2, int N) {
    int i = blockIdx.x * blockDim.x + threadIdx.x;
    if (i >= N * C2T) return;
    int n = i >> 7, c = i & 127;
    float v = out[i] / (den2[n] + 1e-16f) + b2[c];
    out[i] = fmaxf(v, 0.f);
}

// ---------------- launch -----------------------------------------------------
template <typename T>
static float* sym_addr(T& sym) {
    void* p = nullptr;
    cudaGetSymbolAddress(&p, sym);   // host API, not a stream op: capture-safe
    return (float*)p;
}

extern "C" void kernel_launch(void* const* d_in, const int* in_sizes, int n_in,
                              void* d_out, int out_size) {
    const float* x        = (const float*)d_in[0];
    const int*   ei       = (const int*)  d_in[1];
    const float* W1       = (const float*)d_in[2];
    const float* att_src1 = (const float*)d_in[3];
    const float* att_dst1 = (const float*)d_in[4];
    const float* b1       = (const float*)d_in[5];
    const float* W2       = (const float*)d_in[6];
    const float* att_src2 = (const float*)d_in[7];
    const float* att_dst2 = (const float*)d_in[8];
    const float* b2       = (const float*)d_in[9];
    float* out = (float*)d_out;

    // Resolve REAL device addresses of the scratch globals. Passing the
    // symbols directly from host code hands the kernels the host-shadow
    // address (silently "works" via GB300 ATS but touches the wrong copy).
    float* h1   = sym_addr(g_h1);
    float* as1  = sym_addr(g_as1);
    float* ad1  = sym_addr(g_ad1);
    float* den1 = sym_addr(g_den1);
    float* acc1 = sym_addr(g_acc1);
    float* hact = sym_addr(g_hact);
    float* h2   = sym_addr(g_h2);
    float* as2  = sym_addr(g_as2);
    float* ad2  = sym_addr(g_ad2);
    float* den2 = sym_addr(g_den2);

    int N = in_sizes[0] / EIN;   // 50000
    int E = in_sizes[1] / 2;     // 800000
    int Etot = E + N;

    // 0. zero accumulators + output
    zero_all<<<(N * C1T + 255) / 256, 256>>>(acc1, den1, den2, out, N);

    // ---- layer 1 ----
    {
        dim3 grid(C1T / 64, (N + 63) / 64);
        gemm_kernel<EIN><<<grid, 256>>>(x, W1, h1, N, C1T);
    }
    att_dot<<<(N * 4 + 255) / 256, 256>>>(h1, att_src1, att_dst1, as1, ad1, N, 4, 64);
    edge1_kernel<<<((size_t)Etot * 32 + 255) / 256, 256>>>(ei, as1, ad1, den1, h1, acc1, E, N);
    finish1<<<(N * C1T + 255) / 256, 256>>>(acc1, den1, b1, hact, N);

    // ---- layer 2 ----
    {
        dim3 grid(C2T / 64, (N + 63) / 64);
        gemm_kernel<C1T><<<grid, 256>>>(hact, W2, h2, N, C2T);
    }
    att_dot<<<(N + 255) / 256, 256>>>(h2, att_src2, att_dst2, as2, ad2, N, 1, 128);
    edge2_kernel<<<((size_t)Etot * 32 + 255) / 256, 256>>>(ei, as2, ad2, den2, h2, out, E, N);
    finish2<<<(N * C2T + 255) / 256, 256>>>(out, den2, b2, N);
}

// round 8
// speedup vs baseline: 1.6426x; 1.6426x over previous
#include <cuda_runtime.h>
#include <cstdint>

#define NN   50000
#define EIN  128
#define C1T  256   // H1*C1
#define C2T  128   // H2*C2
#define EMAX 800000
#define ETOT (EMAX + NN)

// ---------------- scratch (device globals; allocation is forbidden) ----------
// Only touched through cudaGetSymbolAddress pointers (host-shadow + ATS trap).
__device__ float g_h1 [NN * C1T];
__device__ float g_as1[NN * 4];
__device__ float g_ad1[NN * 4];
__device__ float g_hact[NN * C1T];
__device__ float g_h2 [NN * C2T];
__device__ float g_as2[NN];
__device__ float g_ad2[NN];
__device__ int   g_deg[NN];
__device__ int   g_pos[NN];
__device__ int   g_rowptr[NN + 1];
__device__ int   g_srcs[ETOT];

// ---------------- CSR build --------------------------------------------------
__global__ void csr_init(int* __restrict__ deg, int* __restrict__ pos, int N) {
    int i = blockIdx.x * blockDim.x + threadIdx.x;
    if (i < N) { deg[i] = 1; pos[i] = 0; }   // deg starts at 1: self loop
}

__global__ void csr_count(const int* __restrict__ ei, int* __restrict__ deg, int E) {
    int i = blockIdx.x * blockDim.x + threadIdx.x;
    if (i < E) atomicAdd(&deg[ei[E + i]], 1);
}

// exclusive scan of deg[0..N) into rowptr[0..N], single block of 1024
__global__ void csr_scan(const int* __restrict__ deg, int* __restrict__ rowptr, int N) {
    __shared__ int sums[1024];
    int t = threadIdx.x;
    int chunk = (N + 1023) / 1024;
    int start = t * chunk;
    int end   = min(start + chunk, N);
    int s = 0;
    for (int i = start; i < end; i++) s += deg[i];
    sums[t] = s;
    __syncthreads();
    // Hillis-Steele inclusive scan
    for (int off = 1; off < 1024; off <<= 1) {
        int v = (t >= off) ? sums[t - off] : 0;
        __syncthreads();
        sums[t] += v;
        __syncthreads();
    }
    int run = (t == 0) ? 0 : sums[t - 1];
    for (int i = start; i < end; i++) { rowptr[i] = run; run += deg[i]; }
    if (t == 1023) rowptr[N] = sums[1023];
}

__global__ void csr_scatter(const int* __restrict__ ei,
                            const int* __restrict__ rowptr, int* __restrict__ pos,
                            int* __restrict__ srcs, int E, int N) {
    int i = blockIdx.x * blockDim.x + threadIdx.x;
    if (i >= E + N) return;
    int src, dst;
    if (i < E) { src = ei[i]; dst = ei[E + i]; }
    else       { src = dst = i - E; }
    int p = atomicAdd(&pos[dst], 1);
    srcs[rowptr[dst] + p] = src;
}

// ---------------- fp32 GEMM: 128x128 tile, 8x8 per thread, 256 threads -------
template <int K>
__global__ __launch_bounds__(256)
void gemm128(const float* __restrict__ A, const float* __restrict__ B,
             float* __restrict__ C, int M, int Ncols) {
    __shared__ float As[8][128];   // [k][row]
    __shared__ float Bs[8][128];   // [k][col]
    int tid = threadIdx.x;
    int tx = tid & 15, ty = tid >> 4;
    int row0 = blockIdx.y * 128;
    int col0 = blockIdx.x * 128;

    int a_r = tid >> 1;            // 0..127
    int a_k = (tid & 1) * 4;       // 0 or 4
    int b_k = tid >> 5;            // 0..7
    int b_c = (tid & 31) * 4;      // 0..124

    float acc[8][8];
    #pragma unroll
    for (int i = 0; i < 8; i++)
        #pragma unroll
        for (int j = 0; j < 8; j++) acc[i][j] = 0.f;

    for (int k0 = 0; k0 < K; k0 += 8) {
        float4 av = make_float4(0.f, 0.f, 0.f, 0.f);
        int arow = row0 + a_r;
        if (arow < M)
            av = *reinterpret_cast<const float4*>(A + (size_t)arow * K + k0 + a_k);
        float4 bv = *reinterpret_cast<const float4*>(
            B + (size_t)(k0 + b_k) * Ncols + col0 + b_c);
        __syncthreads();            // previous tile fully consumed
        As[a_k + 0][a_r] = av.x; As[a_k + 1][a_r] = av.y;
        As[a_k + 2][a_r] = av.z; As[a_k + 3][a_r] = av.w;
        *reinterpret_cast<float4*>(&Bs[b_k][b_c]) = bv;
        __syncthreads();

        #pragma unroll
        for (int k = 0; k < 8; k++) {
            float4 ar0 = *reinterpret_cast<const float4*>(&As[k][ty * 8]);
            float4 ar1 = *reinterpret_cast<const float4*>(&As[k][ty * 8 + 4]);
            float4 br0 = *reinterpret_cast<const float4*>(&Bs[k][tx * 8]);
            float4 br1 = *reinterpret_cast<const float4*>(&Bs[k][tx * 8 + 4]);
            float a[8] = {ar0.x, ar0.y, ar0.z, ar0.w, ar1.x, ar1.y, ar1.z, ar1.w};
            float b[8] = {br0.x, br0.y, br0.z, br0.w, br1.x, br1.y, br1.z, br1.w};
            #pragma unroll
            for (int i = 0; i < 8; i++)
                #pragma unroll
                for (int j = 0; j < 8; j++)
                    acc[i][j] += a[i] * b[j];
        }
    }

    #pragma unroll
    for (int i = 0; i < 8; i++) {
        int r = row0 + ty * 8 + i;
        if (r < M) {
            float* cp = C + (size_t)r * Ncols + col0 + tx * 8;
            *reinterpret_cast<float4*>(cp) =
                make_float4(acc[i][0], acc[i][1], acc[i][2], acc[i][3]);
            *reinterpret_cast<float4*>(cp + 4) =
                make_float4(acc[i][4], acc[i][5], acc[i][6], acc[i][7]);
        }
    }
}

// ---------------- attention coefficients ------------------------------------
__global__ void att_dot(const float* __restrict__ h,
                        const float* __restrict__ atts,
                        const float* __restrict__ attd,
                        float* __restrict__ as_, float* __restrict__ ad_,
                        int N, int H, int C) {
    int i = blockIdx.x * blockDim.x + threadIdx.x;
    if (i >= N * H) return;
    int hh = i % H;
    const float* hp = h + (size_t)i * C;
    const float* sp = atts + hh * C;
    const float* dp = attd + hh * C;
    float s = 0.f, d = 0.f;
    for (int c = 0; c < C; c += 4) {
        float4 v = *reinterpret_cast<const float4*>(hp + c);
        float4 a = *reinterpret_cast<const float4*>(sp + c);
        float4 b = *reinterpret_cast<const float4*>(dp + c);
        s += v.x * a.x + v.y * a.y + v.z * a.z + v.w * a.w;
        d += v.x * b.x + v.y * b.y + v.z * b.z + v.w * b.w;
    }
    as_[i] = s;
    ad_[i] = d;
}

// ---------------- layer1 aggregation: warp per dst node ----------------------
// 4 heads x 64ch. Lane handles 8 channels (lane*8..+8) of head (lane>>3).
// Per-head softmax denom: all 8 lanes of a head compute identical weight
// sums, so a per-lane running sum IS the denominator (no reduction needed).
// Fuses normalize + bias + relu.
__global__ __launch_bounds__(256)
void agg1(const int* __restrict__ rowptr, const int* __restrict__ srcs,
          const float* __restrict__ as1, const float* __restrict__ ad1,
          const float* __restrict__ h1, const float* __restrict__ b1,
          float* __restrict__ hact, int N) {
    int w = (blockIdx.x * blockDim.x + threadIdx.x) >> 5;
    if (w >= N) return;
    int lane = threadIdx.x & 31;
    int head = lane >> 3;
    float adn = ad1[w * 4 + head];
    int beg = rowptr[w], end = rowptr[w + 1];

    float4 a0 = make_float4(0.f, 0.f, 0.f, 0.f);
    float4 a1 = make_float4(0.f, 0.f, 0.f, 0.f);
    float den = 0.f;
    for (int j = beg; j < end; j++) {
        int s = srcs[j];                      // warp-broadcast load
        float e = as1[s * 4 + head] + adn;
        e = (e > 0.f) ? e : 0.2f * e;
        float wt = __expf(e);                 // softmax shift-invariant
        den += wt;
        const float4* hp = reinterpret_cast<const float4*>(
            h1 + (size_t)s * C1T) + lane * 2;
        float4 v0 = hp[0], v1 = hp[1];
        a0.x += wt * v0.x; a0.y += wt * v0.y; a0.z += wt * v0.z; a0.w += wt * v0.w;
        a1.x += wt * v1.x; a1.y += wt * v1.y; a1.z += wt * v1.z; a1.w += wt * v1.w;
    }
    float inv = 1.f / (den + 1e-16f);
    int c = lane * 8;
    float4 bb0 = *reinterpret_cast<const float4*>(b1 + c);
    float4 bb1 = *reinterpret_cast<const float4*>(b1 + c + 4);
    float4 o0 = make_float4(fmaxf(a0.x * inv + bb0.x, 0.f),
                            fmaxf(a0.y * inv + bb0.y, 0.f),
                            fmaxf(a0.z * inv + bb0.z, 0.f),
                            fmaxf(a0.w * inv + bb0.w, 0.f));
    float4 o1 = make_float4(fmaxf(a1.x * inv + bb1.x, 0.f),
                            fmaxf(a1.y * inv + bb1.y, 0.f),
                            fmaxf(a1.z * inv + bb1.z, 0.f),
                            fmaxf(a1.w * inv + bb1.w, 0.f));
    float4* op = reinterpret_cast<float4*>(hact + (size_t)w * C1T) + lane * 2;
    op[0] = o0; op[1] = o1;
}

// ---------------- layer2 aggregation: warp per dst node ----------------------
// 1 head x 128ch. Lane handles 4 channels. den identical across all lanes.
__global__ __launch_bounds__(256)
void agg2(const int* __restrict__ rowptr, const int* __restrict__ srcs,
          const float* __restrict__ as2, const float* __restrict__ ad2,
          const float* __restrict__ h2, const float* __restrict__ b2,
          float* __restrict__ out, int N) {
    int w = (blockIdx.x * blockDim.x + threadIdx.x) >> 5;
    if (w >= N) return;
    int lane = threadIdx.x & 31;
    float adn = ad2[w];
    int beg = rowptr[w], end = rowptr[w + 1];

    float4 a = make_float4(0.f, 0.f, 0.f, 0.f);
    float den = 0.f;
    for (int j = beg; j < end; j++) {
        int s = srcs[j];
        float e = as2[s] + adn;
        e = (e > 0.f) ? e : 0.2f * e;
        float wt = __expf(e);
        den += wt;
        float4 v = reinterpret_cast<const float4*>(h2 + (size_t)s * C2T)[lane];
        a.x += wt * v.x; a.y += wt * v.y; a.z += wt * v.z; a.w += wt * v.w;
    }
    float inv = 1.f / (den + 1e-16f);
    int c = lane * 4;
    float4 bb = *reinterpret_cast<const float4*>(b2 + c);
    float4 o = make_float4(fmaxf(a.x * inv + bb.x, 0.f),
                           fmaxf(a.y * inv + bb.y, 0.f),
                           fmaxf(a.z * inv + bb.z, 0.f),
                           fmaxf(a.w * inv + bb.w, 0.f));
    reinterpret_cast<float4*>(out + (size_t)w * C2T)[lane] = o;
}

// ---------------- launch -----------------------------------------------------
template <typename T>
static T* sym_addr(T& sym) {
    void* p = nullptr;
    cudaGetSymbolAddress(&p, sym);   // host API, capture-safe
    return (T*)p;
}
template <typename T, size_t S>
static T* sym_addr(T (&sym)[S]) {
    void* p = nullptr;
    cudaGetSymbolAddress(&p, sym);
    return (T*)p;
}

extern "C" void kernel_launch(void* const* d_in, const int* in_sizes, int n_in,
                              void* d_out, int out_size) {
    const float* x        = (const float*)d_in[0];
    const int*   ei       = (const int*)  d_in[1];
    const float* W1       = (const float*)d_in[2];
    const float* att_src1 = (const float*)d_in[3];
    const float* att_dst1 = (const float*)d_in[4];
    const float* b1       = (const float*)d_in[5];
    const float* W2       = (const float*)d_in[6];
    const float* att_src2 = (const float*)d_in[7];
    const float* att_dst2 = (const float*)d_in[8];
    const float* b2       = (const float*)d_in[9];
    float* out = (float*)d_out;

    float* h1   = sym_addr(g_h1);
    float* as1  = sym_addr(g_as1);
    float* ad1  = sym_addr(g_ad1);
    float* hact = sym_addr(g_hact);
    float* h2   = sym_addr(g_h2);
    float* as2  = sym_addr(g_as2);
    float* ad2  = sym_addr(g_ad2);
    int* deg    = sym_addr(g_deg);
    int* pos    = sym_addr(g_pos);
    int* rowptr = sym_addr(g_rowptr);
    int* srcs   = sym_addr(g_srcs);

    int N = in_sizes[0] / EIN;   // 50000
    int E = in_sizes[1] / 2;     // 800000
    int Etot = E + N;

    // ---- CSR build (dst-bucketed edge list) ----
    csr_init   <<<(N + 255) / 256, 256>>>(deg, pos, N);
    csr_count  <<<(E + 255) / 256, 256>>>(ei, deg, E);
    csr_scan   <<<1, 1024>>>(deg, rowptr, N);
    csr_scatter<<<(Etot + 255) / 256, 256>>>(ei, rowptr, pos, srcs, E, N);

    // ---- layer 1 ----
    {
        dim3 grid(C1T / 128, (N + 127) / 128);
        gemm128<EIN><<<grid, 256>>>(x, W1, h1, N, C1T);
    }
    att_dot<<<(N * 4 + 255) / 256, 256>>>(h1, att_src1, att_dst1, as1, ad1, N, 4, 64);
    agg1<<<((size_t)N * 32 + 255) / 256, 256>>>(rowptr, srcs, as1, ad1, h1, b1, hact, N);

    // ---- layer 2 ----
    {
        dim3 grid(C2T / 128, (N + 127) / 128);
        gemm128<C1T><<<grid, 256>>>(hact, W2, h2, N, C2T);
    }
    att_dot<<<(N + 255) / 256, 256>>>(h2, att_src2, att_dst2, as2, ad2, N, 1, 128);
    agg2<<<((size_t)N * 32 + 255) / 256, 256>>>(rowptr, srcs, as2, ad2, h2, b2, out, N);
}

// round 9
// speedup vs baseline: 2.1817x; 1.3282x over previous
#include <cuda_runtime.h>
#include <cstdint>

#define NN   50000
#define EIN  128
#define C1T  256   // H1*C1
#define C2T  128   // H2*C2
#define EMAX 800000
#define ETOT (EMAX + NN)

// ---------------- scratch (device globals; allocation is forbidden) ----------
// Only touched through cudaGetSymbolAddress pointers (host-shadow + ATS trap).
__device__ float g_h1 [NN * C1T];
__device__ float g_as1[NN * 4];
__device__ float g_ad1[NN * 4];
__device__ float g_hact[NN * C1T];
__device__ float g_h2 [NN * C2T];
__device__ float g_as2[NN];
__device__ float g_ad2[NN];
__device__ int   g_deg[NN];
__device__ int   g_pos[NN];
__device__ int   g_rowptr[NN + 1];
__device__ int   g_srcs[ETOT];

// ---------------- CSR build --------------------------------------------------
__global__ void csr_init(int* __restrict__ deg, int* __restrict__ pos, int N) {
    int i = blockIdx.x * blockDim.x + threadIdx.x;
    if (i < N) { deg[i] = 1; pos[i] = 0; }   // deg starts at 1: self loop
}

__global__ void csr_count(const int* __restrict__ ei, int* __restrict__ deg, int E) {
    int i = blockIdx.x * blockDim.x + threadIdx.x;
    if (i < E) atomicAdd(&deg[ei[E + i]], 1);
}

// exclusive scan of deg[0..N) into rowptr[0..N], single block of 1024
__global__ void csr_scan(const int* __restrict__ deg, int* __restrict__ rowptr, int N) {
    __shared__ int sums[1024];
    int t = threadIdx.x;
    int chunk = (N + 1023) / 1024;
    int start = t * chunk;
    int end   = min(start + chunk, N);
    int s = 0;
    for (int i = start; i < end; i++) s += deg[i];
    sums[t] = s;
    __syncthreads();
    for (int off = 1; off < 1024; off <<= 1) {
        int v = (t >= off) ? sums[t - off] : 0;
        __syncthreads();
        sums[t] += v;
        __syncthreads();
    }
    int run = (t == 0) ? 0 : sums[t - 1];
    for (int i = start; i < end; i++) { rowptr[i] = run; run += deg[i]; }
    if (t == 1023) rowptr[N] = sums[1023];
}

__global__ void csr_scatter(const int* __restrict__ ei,
                            const int* __restrict__ rowptr, int* __restrict__ pos,
                            int* __restrict__ srcs, int E, int N) {
    int i = blockIdx.x * blockDim.x + threadIdx.x;
    if (i >= E + N) return;
    int src, dst;
    if (i < E) { src = ei[i]; dst = ei[E + i]; }
    else       { src = dst = i - E; }
    int p = atomicAdd(&pos[dst], 1);
    srcs[rowptr[dst] + p] = src;
}

// ---------------- tf32 tensor-core GEMM --------------------------------------
// C[M,Ncols] = A[M,K] @ B[K,Ncols], fp32 accumulate, tf32 inputs (cvt.rna).
// BM=128, BN=128, BK=16; 256 threads = 8 warps (2x4), warp tile 64x32.
// Each warp: 4x4 grid of m16n8k8 mma.sync.
__device__ __forceinline__ uint32_t f2tf32(float x) {
    uint32_t r;
    asm("cvt.rna.tf32.f32 %0, %1;" : "=r"(r) : "f"(x));
    return r;
}

__device__ __forceinline__ void mma_tf32(float* d, const uint32_t* a, const uint32_t* b) {
    asm volatile(
        "mma.sync.aligned.m16n8k8.row.col.f32.tf32.tf32.f32 "
        "{%0,%1,%2,%3}, {%4,%5,%6,%7}, {%8,%9}, {%0,%1,%2,%3};"
        : "+f"(d[0]), "+f"(d[1]), "+f"(d[2]), "+f"(d[3])
        : "r"(a[0]), "r"(a[1]), "r"(a[2]), "r"(a[3]), "r"(b[0]), "r"(b[1]));
}

template <int K>
__global__ __launch_bounds__(256)
void gemm_tf32(const float* __restrict__ A, const float* __restrict__ B,
               float* __restrict__ C, int M, int Ncols) {
    __shared__ uint32_t As[16][132];   // [k][m], pad 132 -> conflict-free frags
    __shared__ uint32_t Bs[16][132];   // [k][n]
    int tid  = threadIdx.x;
    int wid  = tid >> 5;
    int lane = tid & 31;
    int row0 = blockIdx.y * 128;
    int col0 = blockIdx.x * 128;
    int m0 = (wid >> 2) * 64;          // warp m origin within tile
    int n0 = (wid & 3) * 32;           // warp n origin
    int rq = lane >> 2;                // 0..7
    int kl = lane & 3;                 // 0..3

    float acc[4][4][4];
    #pragma unroll
    for (int mt = 0; mt < 4; mt++)
        #pragma unroll
        for (int nt = 0; nt < 4; nt++)
            #pragma unroll
            for (int r = 0; r < 4; r++) acc[mt][nt][r] = 0.f;

    for (int k0 = 0; k0 < K; k0 += 16) {
        // stage A: 128 rows x 16 k = 512 float4; thread does l = tid, tid+256
        float4 av[2]; int arow[2], afi[2];
        #pragma unroll
        for (int u = 0; u < 2; u++) {
            int l = tid + u * 256;
            arow[u] = l >> 2;
            afi[u]  = l & 3;
            int gr = row0 + arow[u];
            av[u] = (gr < M)
                ? *reinterpret_cast<const float4*>(A + (size_t)gr * K + k0 + afi[u] * 4)
                : make_float4(0.f, 0.f, 0.f, 0.f);
        }
        // stage B: 16 k x 128 n = 512 float4
        float4 bv[2]; int brow[2], bc4[2];
        #pragma unroll
        for (int u = 0; u < 2; u++) {
            int l = tid + u * 256;
            brow[u] = l >> 5;
            bc4[u]  = l & 31;
            bv[u] = *reinterpret_cast<const float4*>(
                B + (size_t)(k0 + brow[u]) * Ncols + col0 + bc4[u] * 4);
        }
        __syncthreads();   // previous stage fully consumed
        #pragma unroll
        for (int u = 0; u < 2; u++) {
            As[afi[u] * 4 + 0][arow[u]] = f2tf32(av[u].x);
            As[afi[u] * 4 + 1][arow[u]] = f2tf32(av[u].y);
            As[afi[u] * 4 + 2][arow[u]] = f2tf32(av[u].z);
            As[afi[u] * 4 + 3][arow[u]] = f2tf32(av[u].w);
            uint32_t* bp = &Bs[brow[u]][bc4[u] * 4];
            bp[0] = f2tf32(bv[u].x); bp[1] = f2tf32(bv[u].y);
            bp[2] = f2tf32(bv[u].z); bp[3] = f2tf32(bv[u].w);
        }
        __syncthreads();

        #pragma unroll
        for (int k8 = 0; k8 < 16; k8 += 8) {
            int kq = k8 + kl;
            uint32_t af[4][4], bf[4][2];
            #pragma unroll
            for (int mt = 0; mt < 4; mt++) {
                int r = m0 + mt * 16 + rq;
                af[mt][0] = As[kq][r];     af[mt][1] = As[kq][r + 8];
                af[mt][2] = As[kq + 4][r]; af[mt][3] = As[kq + 4][r + 8];
            }
            #pragma unroll
            for (int nt = 0; nt < 4; nt++) {
                int c = n0 + nt * 8 + rq;
                bf[nt][0] = Bs[kq][c];
                bf[nt][1] = Bs[kq + 4][c];
            }
            #pragma unroll
            for (int mt = 0; mt < 4; mt++)
                #pragma unroll
                for (int nt = 0; nt < 4; nt++)
                    mma_tf32(acc[mt][nt], af[mt], bf[nt]);
        }
    }

    // epilogue: per-thread 2-float fragments
    #pragma unroll
    for (int mt = 0; mt < 4; mt++) {
        int r_lo = row0 + m0 + mt * 16 + rq;
        int r_hi = r_lo + 8;
        #pragma unroll
        for (int nt = 0; nt < 4; nt++) {
            int c = col0 + n0 + nt * 8 + 2 * kl;
            if (r_lo < M)
                *reinterpret_cast<float2*>(C + (size_t)r_lo * Ncols + c) =
                    make_float2(acc[mt][nt][0], acc[mt][nt][1]);
            if (r_hi < M)
                *reinterpret_cast<float2*>(C + (size_t)r_hi * Ncols + c) =
                    make_float2(acc[mt][nt][2], acc[mt][nt][3]);
        }
    }
}

// ---------------- attention coefficients ------------------------------------
__global__ void att_dot(const float* __restrict__ h,
                        const float* __restrict__ atts,
                        const float* __restrict__ attd,
                        float* __restrict__ as_, float* __restrict__ ad_,
                        int N, int H, int C) {
    int i = blockIdx.x * blockDim.x + threadIdx.x;
    if (i >= N * H) return;
    int hh = i % H;
    const float* hp = h + (size_t)i * C;
    const float* sp = atts + hh * C;
    const float* dp = attd + hh * C;
    float s = 0.f, d = 0.f;
    for (int c = 0; c < C; c += 4) {
        float4 v = *reinterpret_cast<const float4*>(hp + c);
        float4 a = *reinterpret_cast<const float4*>(sp + c);
        float4 b = *reinterpret_cast<const float4*>(dp + c);
        s += v.x * a.x + v.y * a.y + v.z * a.z + v.w * a.w;
        d += v.x * b.x + v.y * b.y + v.z * b.z + v.w * b.w;
    }
    as_[i] = s;
    ad_[i] = d;
}

// ---------------- layer1 aggregation: warp per dst node ----------------------
__global__ __launch_bounds__(256)
void agg1(const int* __restrict__ rowptr, const int* __restrict__ srcs,
          const float* __restrict__ as1, const float* __restrict__ ad1,
          const float* __restrict__ h1, const float* __restrict__ b1,
          float* __restrict__ hact, int N) {
    int w = (blockIdx.x * blockDim.x + threadIdx.x) >> 5;
    if (w >= N) return;
    int lane = threadIdx.x & 31;
    int head = lane >> 3;
    float adn = ad1[w * 4 + head];
    int beg = rowptr[w], end = rowptr[w + 1];

    float4 a0 = make_float4(0.f, 0.f, 0.f, 0.f);
    float4 a1 = make_float4(0.f, 0.f, 0.f, 0.f);
    float den = 0.f;
    for (int j = beg; j < end; j++) {
        int s = srcs[j];
        float e = as1[s * 4 + head] + adn;
        e = (e > 0.f) ? e : 0.2f * e;
        float wt = __expf(e);                 // softmax shift-invariant
        den += wt;
        const float4* hp = reinterpret_cast<const float4*>(
            h1 + (size_t)s * C1T) + lane * 2;
        float4 v0 = hp[0], v1 = hp[1];
        a0.x += wt * v0.x; a0.y += wt * v0.y; a0.z += wt * v0.z; a0.w += wt * v0.w;
        a1.x += wt * v1.x; a1.y += wt * v1.y; a1.z += wt * v1.z; a1.w += wt * v1.w;
    }
    float inv = 1.f / (den + 1e-16f);
    int c = lane * 8;
    float4 bb0 = *reinterpret_cast<const float4*>(b1 + c);
    float4 bb1 = *reinterpret_cast<const float4*>(b1 + c + 4);
    float4 o0 = make_float4(fmaxf(a0.x * inv + bb0.x, 0.f),
                            fmaxf(a0.y * inv + bb0.y, 0.f),
                            fmaxf(a0.z * inv + bb0.z, 0.f),
                            fmaxf(a0.w * inv + bb0.w, 0.f));
    float4 o1 = make_float4(fmaxf(a1.x * inv + bb1.x, 0.f),
                            fmaxf(a1.y * inv + bb1.y, 0.f),
                            fmaxf(a1.z * inv + bb1.z, 0.f),
                            fmaxf(a1.w * inv + bb1.w, 0.f));
    float4* op = reinterpret_cast<float4*>(hact + (size_t)w * C1T) + lane * 2;
    op[0] = o0; op[1] = o1;
}

// ---------------- layer2 aggregation: warp per dst node ----------------------
__global__ __launch_bounds__(256)
void agg2(const int* __restrict__ rowptr, const int* __restrict__ srcs,
          const float* __restrict__ as2, const float* __restrict__ ad2,
          const float* __restrict__ h2, const float* __restrict__ b2,
          float* __restrict__ out, int N) {
    int w = (blockIdx.x * blockDim.x + threadIdx.x) >> 5;
    if (w >= N) return;
    int lane = threadIdx.x & 31;
    float adn = ad2[w];
    int beg = rowptr[w], end = rowptr[w + 1];

    float4 a = make_float4(0.f, 0.f, 0.f, 0.f);
    float den = 0.f;
    for (int j = beg; j < end; j++) {
        int s = srcs[j];
        float e = as2[s] + adn;
        e = (e > 0.f) ? e : 0.2f * e;
        float wt = __expf(e);
        den += wt;
        float4 v = reinterpret_cast<const float4*>(h2 + (size_t)s * C2T)[lane];
        a.x += wt * v.x; a.y += wt * v.y; a.z += wt * v.z; a.w += wt * v.w;
    }
    float inv = 1.f / (den + 1e-16f);
    int c = lane * 4;
    float4 bb = *reinterpret_cast<const float4*>(b2 + c);
    float4 o = make_float4(fmaxf(a.x * inv + bb.x, 0.f),
                           fmaxf(a.y * inv + bb.y, 0.f),
                           fmaxf(a.z * inv + bb.z, 0.f),
                           fmaxf(a.w * inv + bb.w, 0.f));
    reinterpret_cast<float4*>(out + (size_t)w * C2T)[lane] = o;
}

// ---------------- launch -----------------------------------------------------
template <typename T>
static T* sym_addr(T& sym) {
    void* p = nullptr;
    cudaGetSymbolAddress(&p, sym);   // host API, capture-safe
    return (T*)p;
}
template <typename T, size_t S>
static T* sym_addr(T (&sym)[S]) {
    void* p = nullptr;
    cudaGetSymbolAddress(&p, sym);
    return (T*)p;
}

extern "C" void kernel_launch(void* const* d_in, const int* in_sizes, int n_in,
                              void* d_out, int out_size) {
    const float* x        = (const float*)d_in[0];
    const int*   ei       = (const int*)  d_in[1];
    const float* W1       = (const float*)d_in[2];
    const float* att_src1 = (const float*)d_in[3];
    const float* att_dst1 = (const float*)d_in[4];
    const float* b1       = (const float*)d_in[5];
    const float* W2       = (const float*)d_in[6];
    const float* att_src2 = (const float*)d_in[7];
    const float* att_dst2 = (const float*)d_in[8];
    const float* b2       = (const float*)d_in[9];
    float* out = (float*)d_out;

    float* h1   = sym_addr(g_h1);
    float* as1  = sym_addr(g_as1);
    float* ad1  = sym_addr(g_ad1);
    float* hact = sym_addr(g_hact);
    float* h2   = sym_addr(g_h2);
    float* as2  = sym_addr(g_as2);
    float* ad2  = sym_addr(g_ad2);
    int* deg    = sym_addr(g_deg);
    int* pos    = sym_addr(g_pos);
    int* rowptr = sym_addr(g_rowptr);
    int* srcs   = sym_addr(g_srcs);

    int N = in_sizes[0] / EIN;   // 50000
    int E = in_sizes[1] / 2;     // 800000
    int Etot = E + N;

    // ---- CSR build (dst-bucketed edge list) ----
    csr_init   <<<(N + 255) / 256, 256>>>(deg, pos, N);
    csr_count  <<<(E + 255) / 256, 256>>>(ei, deg, E);
    csr_scan   <<<1, 1024>>>(deg, rowptr, N);
    csr_scatter<<<(Etot + 255) / 256, 256>>>(ei, rowptr, pos, srcs, E, N);

    // ---- layer 1 ----
    {
        dim3 grid(C1T / 128, (N + 127) / 128);
        gemm_tf32<EIN><<<grid, 256>>>(x, W1, h1, N, C1T);
    }
    att_dot<<<(N * 4 + 255) / 256, 256>>>(h1, att_src1, att_dst1, as1, ad1, N, 4, 64);
    agg1<<<((size_t)N * 32 + 255) / 256, 256>>>(rowptr, srcs, as1, ad1, h1, b1, hact, N);

    // ---- layer 2 ----
    {
        dim3 grid(C2T / 128, (N + 127) / 128);
        gemm_tf32<C1T><<<grid, 256>>>(hact, W2, h2, N, C2T);
    }
    att_dot<<<(N + 255) / 256, 256>>>(h2, att_src2, att_dst2, as2, ad2, N, 1, 128);
    agg2<<<((size_t)N * 32 + 255) / 256, 256>>>(rowptr, srcs, as2, ad2, h2, b2, out, N);
}

// round 10
// speedup vs baseline: 2.1836x; 1.0008x over previous
#include <cuda_runtime.h>
#include <cstdint>

#define NN   50000
#define EIN  128
#define C1T  256   // H1*C1
#define C2T  128   // H2*C2
#define EMAX 800000
#define ETOT (EMAX + NN)

// ---------------- scratch (device globals; allocation is forbidden) ----------
// Only touched through cudaGetSymbolAddress pointers (host-shadow + ATS trap).
__device__ float g_h1 [NN * C1T];
__device__ float g_as1[NN * 4];
__device__ float g_ad1[NN * 4];
__device__ float g_hact[NN * C1T];
__device__ float g_h2 [NN * C2T];
__device__ float g_as2[NN];
__device__ float g_ad2[NN];
__device__ int   g_deg[NN];
__device__ int   g_pos[NN];
__device__ int   g_rowptr[NN + 1];
__device__ int   g_srcs[ETOT];

// ---------------- CSR build --------------------------------------------------
__global__ void csr_init(int* __restrict__ deg, int* __restrict__ pos, int N) {
    int i = blockIdx.x * blockDim.x + threadIdx.x;
    if (i < N) { deg[i] = 1; pos[i] = 0; }   // deg starts at 1: self loop
}

__global__ void csr_count(const int* __restrict__ ei, int* __restrict__ deg, int E) {
    int i = blockIdx.x * blockDim.x + threadIdx.x;
    if (i < E) atomicAdd(&deg[ei[E + i]], 1);
}

// exclusive scan of deg[0..N) into rowptr[0..N], single block of 1024
__global__ void csr_scan(const int* __restrict__ deg, int* __restrict__ rowptr, int N) {
    __shared__ int sums[1024];
    int t = threadIdx.x;
    int chunk = (N + 1023) / 1024;
    int start = t * chunk;
    int end   = min(start + chunk, N);
    int s = 0;
    for (int i = start; i < end; i++) s += deg[i];
    sums[t] = s;
    __syncthreads();
    for (int off = 1; off < 1024; off <<= 1) {
        int v = (t >= off) ? sums[t - off] : 0;
        __syncthreads();
        sums[t] += v;
        __syncthreads();
    }
    int run = (t == 0) ? 0 : sums[t - 1];
    for (int i = start; i < end; i++) { rowptr[i] = run; run += deg[i]; }
    if (t == 1023) rowptr[N] = sums[1023];
}

__global__ void csr_scatter(const int* __restrict__ ei,
                            const int* __restrict__ rowptr, int* __restrict__ pos,
                            int* __restrict__ srcs, int E, int N) {
    int i = blockIdx.x * blockDim.x + threadIdx.x;
    if (i >= E + N) return;
    int src, dst;
    if (i < E) { src = ei[i]; dst = ei[E + i]; }
    else       { src = dst = i - E; }
    int p = atomicAdd(&pos[dst], 1);
    srcs[rowptr[dst] + p] = src;
}

// ---------------- tf32 tensor-core GEMM --------------------------------------
// C[M,Ncols] = A[M,K] @ B[K,Ncols], fp32 accumulate, tf32 inputs (cvt.rna).
// BM=128, BN=128, BK=16; 256 threads = 8 warps (2x4), warp tile 64x32.
// Each warp: 4x4 grid of m16n8k8 mma.sync.
__device__ __forceinline__ uint32_t f2tf32(float x) {
    uint32_t r;
    asm("cvt.rna.tf32.f32 %0, %1;" : "=r"(r) : "f"(x));
    return r;
}

__device__ __forceinline__ void mma_tf32(float* d, const uint32_t* a, const uint32_t* b) {
    asm volatile(
        "mma.sync.aligned.m16n8k8.row.col.f32.tf32.tf32.f32 "
        "{%0,%1,%2,%3}, {%4,%5,%6,%7}, {%8,%9}, {%0,%1,%2,%3};"
        : "+f"(d[0]), "+f"(d[1]), "+f"(d[2]), "+f"(d[3])
        : "r"(a[0]), "r"(a[1]), "r"(a[2]), "r"(a[3]), "r"(b[0]), "r"(b[1]));
}

template <int K>
__global__ __launch_bounds__(256)
void gemm_tf32(const float* __restrict__ A, const float* __restrict__ B,
               float* __restrict__ C, int M, int Ncols) {
    __shared__ uint32_t As[16][132];   // [k][m], pad 132 -> conflict-free frags
    __shared__ uint32_t Bs[16][132];   // [k][n]
    int tid  = threadIdx.x;
    int wid  = tid >> 5;
    int lane = tid & 31;
    int row0 = blockIdx.y * 128;
    int col0 = blockIdx.x * 128;
    int m0 = (wid >> 2) * 64;          // warp m origin within tile
    int n0 = (wid & 3) * 32;           // warp n origin
    int rq = lane >> 2;                // 0..7
    int kl = lane & 3;                 // 0..3

    float acc[4][4][4];
    #pragma unroll
    for (int mt = 0; mt < 4; mt++)
        #pragma unroll
        for (int nt = 0; nt < 4; nt++)
            #pragma unroll
            for (int r = 0; r < 4; r++) acc[mt][nt][r] = 0.f;

    for (int k0 = 0; k0 < K; k0 += 16) {
        // stage A: 128 rows x 16 k = 512 float4; thread does l = tid, tid+256
        float4 av[2]; int arow[2], afi[2];
        #pragma unroll
        for (int u = 0; u < 2; u++) {
            int l = tid + u * 256;
            arow[u] = l >> 2;
            afi[u]  = l & 3;
            int gr = row0 + arow[u];
            av[u] = (gr < M)
                ? *reinterpret_cast<const float4*>(A + (size_t)gr * K + k0 + afi[u] * 4)
                : make_float4(0.f, 0.f, 0.f, 0.f);
        }
        // stage B: 16 k x 128 n = 512 float4
        float4 bv[2]; int brow[2], bc4[2];
        #pragma unroll
        for (int u = 0; u < 2; u++) {
            int l = tid + u * 256;
            brow[u] = l >> 5;
            bc4[u]  = l & 31;
            bv[u] = *reinterpret_cast<const float4*>(
                B + (size_t)(k0 + brow[u]) * Ncols + col0 + bc4[u] * 4);
        }
        __syncthreads();   // previous stage fully consumed
        #pragma unroll
        for (int u = 0; u < 2; u++) {
            As[afi[u] * 4 + 0][arow[u]] = f2tf32(av[u].x);
            As[afi[u] * 4 + 1][arow[u]] = f2tf32(av[u].y);
            As[afi[u] * 4 + 2][arow[u]] = f2tf32(av[u].z);
            As[afi[u] * 4 + 3][arow[u]] = f2tf32(av[u].w);
            uint32_t* bp = &Bs[brow[u]][bc4[u] * 4];
            bp[0] = f2tf32(bv[u].x); bp[1] = f2tf32(bv[u].y);
            bp[2] = f2tf32(bv[u].z); bp[3] = f2tf32(bv[u].w);
        }
        __syncthreads();

        #pragma unroll
        for (int k8 = 0; k8 < 16; k8 += 8) {
            int kq = k8 + kl;
            uint32_t af[4][4], bf[4][2];
            #pragma unroll
            for (int mt = 0; mt < 4; mt++) {
                int r = m0 + mt * 16 + rq;
                af[mt][0] = As[kq][r];     af[mt][1] = As[kq][r + 8];
                af[mt][2] = As[kq + 4][r]; af[mt][3] = As[kq + 4][r + 8];
            }
            #pragma unroll
            for (int nt = 0; nt < 4; nt++) {
                int c = n0 + nt * 8 + rq;
                bf[nt][0] = Bs[kq][c];
                bf[nt][1] = Bs[kq + 4][c];
            }
            #pragma unroll
            for (int mt = 0; mt < 4; mt++)
                #pragma unroll
                for (int nt = 0; nt < 4; nt++)
                    mma_tf32(acc[mt][nt], af[mt], bf[nt]);
        }
    }

    // epilogue: per-thread 2-float fragments
    #pragma unroll
    for (int mt = 0; mt < 4; mt++) {
        int r_lo = row0 + m0 + mt * 16 + rq;
        int r_hi = r_lo + 8;
        #pragma unroll
        for (int nt = 0; nt < 4; nt++) {
            int c = col0 + n0 + nt * 8 + 2 * kl;
            if (r_lo < M)
                *reinterpret_cast<float2*>(C + (size_t)r_lo * Ncols + c) =
                    make_float2(acc[mt][nt][0], acc[mt][nt][1]);
            if (r_hi < M)
                *reinterpret_cast<float2*>(C + (size_t)r_hi * Ncols + c) =
                    make_float2(acc[mt][nt][2], acc[mt][nt][3]);
        }
    }
}

// ---------------- attention coefficients ------------------------------------
__global__ void att_dot(const float* __restrict__ h,
                        const float* __restrict__ atts,
                        const float* __restrict__ attd,
                        float* __restrict__ as_, float* __restrict__ ad_,
                        int N, int H, int C) {
    int i = blockIdx.x * blockDim.x + threadIdx.x;
    if (i >= N * H) return;
    int hh = i % H;
    const float* hp = h + (size_t)i * C;
    const float* sp = atts + hh * C;
    const float* dp = attd + hh * C;
    float s = 0.f, d = 0.f;
    for (int c = 0; c < C; c += 4) {
        float4 v = *reinterpret_cast<const float4*>(hp + c);
        float4 a = *reinterpret_cast<const float4*>(sp + c);
        float4 b = *reinterpret_cast<const float4*>(dp + c);
        s += v.x * a.x + v.y * a.y + v.z * a.z + v.w * a.w;
        d += v.x * b.x + v.y * b.y + v.z * b.z + v.w * b.w;
    }
    as_[i] = s;
    ad_[i] = d;
}

// ---------------- layer1 aggregation: warp per dst node ----------------------
__global__ __launch_bounds__(256)
void agg1(const int* __restrict__ rowptr, const int* __restrict__ srcs,
          const float* __restrict__ as1, const float* __restrict__ ad1,
          const float* __restrict__ h1, const float* __restrict__ b1,
          float* __restrict__ hact, int N) {
    int w = (blockIdx.x * blockDim.x + threadIdx.x) >> 5;
    if (w >= N) return;
    int lane = threadIdx.x & 31;
    int head = lane >> 3;
    float adn = ad1[w * 4 + head];
    int beg = rowptr[w], end = rowptr[w + 1];

    float4 a0 = make_float4(0.f, 0.f, 0.f, 0.f);
    float4 a1 = make_float4(0.f, 0.f, 0.f, 0.f);
    float den = 0.f;
    for (int j = beg; j < end; j++) {
        int s = srcs[j];
        float e = as1[s * 4 + head] + adn;
        e = (e > 0.f) ? e : 0.2f * e;
        float wt = __expf(e);                 // softmax shift-invariant
        den += wt;
        const float4* hp = reinterpret_cast<const float4*>(
            h1 + (size_t)s * C1T) + lane * 2;
        float4 v0 = hp[0], v1 = hp[1];
        a0.x += wt * v0.x; a0.y += wt * v0.y; a0.z += wt * v0.z; a0.w += wt * v0.w;
        a1.x += wt * v1.x; a1.y += wt * v1.y; a1.z += wt * v1.z; a1.w += wt * v1.w;
    }
    float inv = 1.f / (den + 1e-16f);
    int c = lane * 8;
    float4 bb0 = *reinterpret_cast<const float4*>(b1 + c);
    float4 bb1 = *reinterpret_cast<const float4*>(b1 + c + 4);
    float4 o0 = make_float4(fmaxf(a0.x * inv + bb0.x, 0.f),
                            fmaxf(a0.y * inv + bb0.y, 0.f),
                            fmaxf(a0.z * inv + bb0.z, 0.f),
                            fmaxf(a0.w * inv + bb0.w, 0.f));
    float4 o1 = make_float4(fmaxf(a1.x * inv + bb1.x, 0.f),
                            fmaxf(a1.y * inv + bb1.y, 0.f),
                            fmaxf(a1.z * inv + bb1.z, 0.f),
                            fmaxf(a1.w * inv + bb1.w, 0.f));
    float4* op = reinterpret_cast<float4*>(hact + (size_t)w * C1T) + lane * 2;
    op[0] = o0; op[1] = o1;
}

// ---------------- layer2 aggregation: warp per dst node ----------------------
__global__ __launch_bounds__(256)
void agg2(const int* __restrict__ rowptr, const int* __restrict__ srcs,
          const float* __restrict__ as2, const float* __restrict__ ad2,
          const float* __restrict__ h2, const float* __restrict__ b2,
          float* __restrict__ out, int N) {
    int w = (blockIdx.x * blockDim.x + threadIdx.x) >> 5;
    if (w >= N) return;
    int lane = threadIdx.x & 31;
    float adn = ad2[w];
    int beg = rowptr[w], end = rowptr[w + 1];

    float4 a = make_float4(0.f, 0.f, 0.f, 0.f);
    float den = 0.f;
    for (int j = beg; j < end; j++) {
        int s = srcs[j];
        float e = as2[s] + adn;
        e = (e > 0.f) ? e : 0.2f * e;
        float wt = __expf(e);
        den += wt;
        float4 v = reinterpret_cast<const float4*>(h2 + (size_t)s * C2T)[lane];
        a.x += wt * v.x; a.y += wt * v.y; a.z += wt * v.z; a.w += wt * v.w;
    }
    float inv = 1.f / (den + 1e-16f);
    int c = lane * 4;
    float4 bb = *reinterpret_cast<const float4*>(b2 + c);
    float4 o = make_float4(fmaxf(a.x * inv + bb.x, 0.f),
                           fmaxf(a.y * inv + bb.y, 0.f),
                           fmaxf(a.z * inv + bb.z, 0.f),
                           fmaxf(a.w * inv + bb.w, 0.f));
    reinterpret_cast<float4*>(out + (size_t)w * C2T)[lane] = o;
}

// ---------------- launch -----------------------------------------------------
template <typename T>
static T* sym_addr(T& sym) {
    void* p = nullptr;
    cudaGetSymbolAddress(&p, sym);   // host API, capture-safe
    return (T*)p;
}
template <typename T, size_t S>
static T* sym_addr(T (&sym)[S]) {
    void* p = nullptr;
    cudaGetSymbolAddress(&p, sym);
    return (T*)p;
}

extern "C" void kernel_launch(void* const* d_in, const int* in_sizes, int n_in,
                              void* d_out, int out_size) {
    const float* x        = (const float*)d_in[0];
    const int*   ei       = (const int*)  d_in[1];
    const float* W1       = (const float*)d_in[2];
    const float* att_src1 = (const float*)d_in[3];
    const float* att_dst1 = (const float*)d_in[4];
    const float* b1       = (const float*)d_in[5];
    const float* W2       = (const float*)d_in[6];
    const float* att_src2 = (const float*)d_in[7];
    const float* att_dst2 = (const float*)d_in[8];
    const float* b2       = (const float*)d_in[9];
    float* out = (float*)d_out;

    float* h1   = sym_addr(g_h1);
    float* as1  = sym_addr(g_as1);
    float* ad1  = sym_addr(g_ad1);
    float* hact = sym_addr(g_hact);
    float* h2   = sym_addr(g_h2);
    float* as2  = sym_addr(g_as2);
    float* ad2  = sym_addr(g_ad2);
    int* deg    = sym_addr(g_deg);
    int* pos    = sym_addr(g_pos);
    int* rowptr = sym_addr(g_rowptr);
    int* srcs   = sym_addr(g_srcs);

    int N = in_sizes[0] / EIN;   // 50000
    int E = in_sizes[1] / 2;     // 800000
    int Etot = E + N;

    // ---- CSR build (dst-bucketed edge list) ----
    csr_init   <<<(N + 255) / 256, 256>>>(deg, pos, N);
    csr_count  <<<(E + 255) / 256, 256>>>(ei, deg, E);
    csr_scan   <<<1, 1024>>>(deg, rowptr, N);
    csr_scatter<<<(Etot + 255) / 256, 256>>>(ei, rowptr, pos, srcs, E, N);

    // ---- layer 1 ----
    {
        dim3 grid(C1T / 128, (N + 127) / 128);
        gemm_tf32<EIN><<<grid, 256>>>(x, W1, h1, N, C1T);
    }
    att_dot<<<(N * 4 + 255) / 256, 256>>>(h1, att_src1, att_dst1, as1, ad1, N, 4, 64);
    agg1<<<((size_t)N * 32 + 255) / 256, 256>>>(rowptr, srcs, as1, ad1, h1, b1, hact, N);

    // ---- layer 2 ----
    {
        dim3 grid(C2T / 128, (N + 127) / 128);
        gemm_tf32<C1T><<<grid, 256>>>(hact, W2, h2, N, C2T);
    }
    att_dot<<<(N + 255) / 256, 256>>>(h2, att_src2, att_dst2, as2, ad2, N, 1, 128);
    agg2<<<((size_t)N * 32 + 255) / 256, 256>>>(rowptr, srcs, as2, ad2, h2, b2, out, N);
}

// round 11
// speedup vs baseline: 2.2564x; 1.0334x over previous
#include <cuda_runtime.h>
#include <cuda_fp16.h>
#include <cstdint>

#define NN   50000
#define EIN  128
#define C1T  256   // H1*C1
#define C2T  128   // H2*C2
#define EMAX 800000
#define ETOT (EMAX + NN)

// ---------------- scratch (device globals; allocation is forbidden) ----------
// Only touched through cudaGetSymbolAddress pointers (host-shadow + ATS trap).
__device__ __align__(256) __half g_h1h  [NN * C1T];   // gemm1 out (fp16)
__device__ __align__(256) __half g_hacth[NN * C1T];   // layer2 input (fp16)
__device__ __align__(256) __half g_h2h  [NN * C2T];   // gemm2 out (fp16)
__device__ float g_as1[NN * 4];
__device__ float g_ad1[NN * 4];
__device__ float g_as2[NN];
__device__ float g_ad2[NN];
__device__ int   g_deg[NN];
__device__ int   g_pos[NN];
__device__ int   g_rowptr[NN + 1];
__device__ int   g_srcs[ETOT];

// ---------------- CSR build --------------------------------------------------
__global__ void csr_init(int* __restrict__ deg, int* __restrict__ pos, int N) {
    int i = blockIdx.x * blockDim.x + threadIdx.x;
    if (i < N) { deg[i] = 1; pos[i] = 0; }   // deg starts at 1: self loop
}

__global__ void csr_count(const int* __restrict__ ei, int* __restrict__ deg, int E) {
    int i = blockIdx.x * blockDim.x + threadIdx.x;
    if (i < E) atomicAdd(&deg[ei[E + i]], 1);
}

// exclusive scan of deg[0..N) into rowptr[0..N], single block of 1024
__global__ void csr_scan(const int* __restrict__ deg, int* __restrict__ rowptr, int N) {
    __shared__ int sums[1024];
    int t = threadIdx.x;
    int chunk = (N + 1023) / 1024;
    int start = t * chunk;
    int end   = min(start + chunk, N);
    int s = 0;
    for (int i = start; i < end; i++) s += deg[i];
    sums[t] = s;
    __syncthreads();
    for (int off = 1; off < 1024; off <<= 1) {
        int v = (t >= off) ? sums[t - off] : 0;
        __syncthreads();
        sums[t] += v;
        __syncthreads();
    }
    int run = (t == 0) ? 0 : sums[t - 1];
    for (int i = start; i < end; i++) { rowptr[i] = run; run += deg[i]; }
    if (t == 1023) rowptr[N] = sums[1023];
}

__global__ void csr_scatter(const int* __restrict__ ei,
                            const int* __restrict__ rowptr, int* __restrict__ pos,
                            int* __restrict__ srcs, int E, int N) {
    int i = blockIdx.x * blockDim.x + threadIdx.x;
    if (i >= E + N) return;
    int src, dst;
    if (i < E) { src = ei[i]; dst = ei[E + i]; }
    else       { src = dst = i - E; }
    int p = atomicAdd(&pos[dst], 1);
    srcs[rowptr[dst] + p] = src;
}

// ---------------- tf32 tensor-core GEMM --------------------------------------
// C[M,Ncols] = A[M,K] @ B[K,Ncols]; A fp32 or fp16, B fp32, out fp16.
// BM=128, BN=128, BK=16; 256 threads = 8 warps (2x4), warp tile 64x32.
__device__ __forceinline__ uint32_t f2tf32(float x) {
    uint32_t r;
    asm("cvt.rna.tf32.f32 %0, %1;" : "=r"(r) : "f"(x));
    return r;
}

__device__ __forceinline__ void mma_tf32(float* d, const uint32_t* a, const uint32_t* b) {
    asm volatile(
        "mma.sync.aligned.m16n8k8.row.col.f32.tf32.tf32.f32 "
        "{%0,%1,%2,%3}, {%4,%5,%6,%7}, {%8,%9}, {%0,%1,%2,%3};"
        : "+f"(d[0]), "+f"(d[1]), "+f"(d[2]), "+f"(d[3])
        : "r"(a[0]), "r"(a[1]), "r"(a[2]), "r"(a[3]), "r"(b[0]), "r"(b[1]));
}

template <int K, typename AT>
__global__ __launch_bounds__(256)
void gemm_tf32(const AT* __restrict__ A, const float* __restrict__ B,
               __half* __restrict__ C, int M, int Ncols) {
    __shared__ uint32_t As[16][132];   // [k][m], pad -> conflict-free frags
    __shared__ uint32_t Bs[16][132];   // [k][n]
    int tid  = threadIdx.x;
    int wid  = tid >> 5;
    int lane = tid & 31;
    int row0 = blockIdx.y * 128;
    int col0 = blockIdx.x * 128;
    int m0 = (wid >> 2) * 64;
    int n0 = (wid & 3) * 32;
    int rq = lane >> 2;                // 0..7
    int kl = lane & 3;                 // 0..3

    float acc[4][4][4];
    #pragma unroll
    for (int mt = 0; mt < 4; mt++)
        #pragma unroll
        for (int nt = 0; nt < 4; nt++)
            #pragma unroll
            for (int r = 0; r < 4; r++) acc[mt][nt][r] = 0.f;

    for (int k0 = 0; k0 < K; k0 += 16) {
        // ---- stage A: 128 rows x 16 k ----
        float a_f[2][4]; int a_row[2], a_ko[2]; int a_n;
        if (sizeof(AT) == 4) {
            a_n = 2;                       // two float4 per thread
            #pragma unroll
            for (int u = 0; u < 2; u++) {
                int l = tid + u * 256;
                a_row[u] = l >> 2;
                a_ko[u]  = (l & 3) * 4;
                int gr = row0 + a_row[u];
                float4 v = (gr < M)
                    ? *reinterpret_cast<const float4*>(
                          (const float*)A + (size_t)gr * K + k0 + a_ko[u])
                    : make_float4(0.f, 0.f, 0.f, 0.f);
                a_f[u][0] = v.x; a_f[u][1] = v.y; a_f[u][2] = v.z; a_f[u][3] = v.w;
            }
        } else {
            a_n = 1;                       // one uint4 = 8 halves per thread
            a_row[0] = tid >> 1;
            a_ko[0]  = (tid & 1) * 8;
            int gr = row0 + a_row[0];
            uint4 v = (gr < M)
                ? *reinterpret_cast<const uint4*>(
                      (const __half*)A + (size_t)gr * K + k0 + a_ko[0])
                : make_uint4(0u, 0u, 0u, 0u);
            const __half2* hp = reinterpret_cast<const __half2*>(&v);
            #pragma unroll
            for (int j = 0; j < 4; j++) {
                float2 f = __half22float2(hp[j]);
                a_f[j >> 1][(j & 1) * 2 + 0] = f.x;   // pack 8 floats into a_f[0..1][0..3]
                a_f[j >> 1][(j & 1) * 2 + 1] = f.y;
            }
        }
        // ---- stage B: 16 k x 128 n (fp32 weights) ----
        float4 bv[2]; int brow[2], bc4[2];
        #pragma unroll
        for (int u = 0; u < 2; u++) {
            int l = tid + u * 256;
            brow[u] = l >> 5;
            bc4[u]  = l & 31;
            bv[u] = *reinterpret_cast<const float4*>(
                B + (size_t)(k0 + brow[u]) * Ncols + col0 + bc4[u] * 4);
        }
        __syncthreads();   // previous stage fully consumed
        if (sizeof(AT) == 4) {
            #pragma unroll
            for (int u = 0; u < 2; u++)
                #pragma unroll
                for (int j = 0; j < 4; j++)
                    As[a_ko[u] + j][a_row[u]] = f2tf32(a_f[u][j]);
        } else {
            #pragma unroll
            for (int j = 0; j < 8; j++)
                As[a_ko[0] + j][a_row[0]] = f2tf32(a_f[j >> 2][j & 3]);
        }
        #pragma unroll
        for (int u = 0; u < 2; u++) {
            uint32_t* bp = &Bs[brow[u]][bc4[u] * 4];
            bp[0] = f2tf32(bv[u].x); bp[1] = f2tf32(bv[u].y);
            bp[2] = f2tf32(bv[u].z); bp[3] = f2tf32(bv[u].w);
        }
        __syncthreads();

        #pragma unroll
        for (int k8 = 0; k8 < 16; k8 += 8) {
            int kq = k8 + kl;
            uint32_t af[4][4], bf[4][2];
            #pragma unroll
            for (int mt = 0; mt < 4; mt++) {
                int r = m0 + mt * 16 + rq;
                af[mt][0] = As[kq][r];     af[mt][1] = As[kq][r + 8];
                af[mt][2] = As[kq + 4][r]; af[mt][3] = As[kq + 4][r + 8];
            }
            #pragma unroll
            for (int nt = 0; nt < 4; nt++) {
                int c = n0 + nt * 8 + rq;
                bf[nt][0] = Bs[kq][c];
                bf[nt][1] = Bs[kq + 4][c];
            }
            #pragma unroll
            for (int mt = 0; mt < 4; mt++)
                #pragma unroll
                for (int nt = 0; nt < 4; nt++)
                    mma_tf32(acc[mt][nt], af[mt], bf[nt]);
        }
    }

    // epilogue: fp16 output, per-thread half2 fragments
    #pragma unroll
    for (int mt = 0; mt < 4; mt++) {
        int r_lo = row0 + m0 + mt * 16 + rq;
        int r_hi = r_lo + 8;
        #pragma unroll
        for (int nt = 0; nt < 4; nt++) {
            int c = col0 + n0 + nt * 8 + 2 * kl;
            if (r_lo < M)
                *reinterpret_cast<__half2*>(C + (size_t)r_lo * Ncols + c) =
                    __floats2half2_rn(acc[mt][nt][0], acc[mt][nt][1]);
            if (r_hi < M)
                *reinterpret_cast<__half2*>(C + (size_t)r_hi * Ncols + c) =
                    __floats2half2_rn(acc[mt][nt][2], acc[mt][nt][3]);
        }
    }
}

// ---------------- attention coefficients (fp16 features, fp32 math) ---------
__global__ void att_dot(const __half* __restrict__ h,
                        const float* __restrict__ atts,
                        const float* __restrict__ attd,
                        float* __restrict__ as_, float* __restrict__ ad_,
                        int N, int H, int C) {
    int i = blockIdx.x * blockDim.x + threadIdx.x;
    if (i >= N * H) return;
    int hh = i % H;
    const __half2* hp = reinterpret_cast<const __half2*>(h + (size_t)i * C);
    const float* sp = atts + hh * C;
    const float* dp = attd + hh * C;
    float s = 0.f, d = 0.f;
    for (int c = 0; c < C / 2; c++) {
        float2 v = __half22float2(hp[c]);
        s += v.x * sp[2 * c] + v.y * sp[2 * c + 1];
        d += v.x * dp[2 * c] + v.y * dp[2 * c + 1];
    }
    as_[i] = s;
    ad_[i] = d;
}

// ---------------- layer1 aggregation: warp per dst node ----------------------
// 4 heads x 64ch fp16 messages. Lane: 8 channels (one uint4) of head lane>>3.
// Per-lane running den == per-head softmax denom (identical across head lanes).
__global__ __launch_bounds__(256)
void agg1(const int* __restrict__ rowptr, const int* __restrict__ srcs,
          const float* __restrict__ as1, const float* __restrict__ ad1,
          const __half* __restrict__ h1, const float* __restrict__ b1,
          __half* __restrict__ hact, int N) {
    int w = (blockIdx.x * blockDim.x + threadIdx.x) >> 5;
    if (w >= N) return;
    int lane = threadIdx.x & 31;
    int head = lane >> 3;
    float adn = ad1[w * 4 + head];
    int beg = rowptr[w], end = rowptr[w + 1];

    float a[8] = {0.f, 0.f, 0.f, 0.f, 0.f, 0.f, 0.f, 0.f};
    float den = 0.f;
    for (int j = beg; j < end; j++) {
        int s = srcs[j];
        float e = as1[s * 4 + head] + adn;
        e = (e > 0.f) ? e : 0.2f * e;
        float wt = __expf(e);                 // softmax shift-invariant
        den += wt;
        uint4 hv = reinterpret_cast<const uint4*>(h1 + (size_t)s * C1T)[lane];
        const __half2* hp = reinterpret_cast<const __half2*>(&hv);
        #pragma unroll
        for (int q = 0; q < 4; q++) {
            float2 f = __half22float2(hp[q]);
            a[2 * q]     += wt * f.x;
            a[2 * q + 1] += wt * f.y;
        }
    }
    float inv = 1.f / (den + 1e-16f);
    int c = lane * 8;
    __half2 o[4];
    #pragma unroll
    for (int q = 0; q < 4; q++) {
        float ox = fmaxf(a[2 * q]     * inv + b1[c + 2 * q],     0.f);
        float oy = fmaxf(a[2 * q + 1] * inv + b1[c + 2 * q + 1], 0.f);
        o[q] = __floats2half2_rn(ox, oy);
    }
    reinterpret_cast<uint4*>(hact + (size_t)w * C1T)[lane] =
        *reinterpret_cast<const uint4*>(o);
}

// ---------------- layer2 aggregation: warp per dst node ----------------------
// 1 head x 128ch fp16 messages. Lane: 4 channels (one uint2). fp32 output.
__global__ __launch_bounds__(256)
void agg2(const int* __restrict__ rowptr, const int* __restrict__ srcs,
          const float* __restrict__ as2, const float* __restrict__ ad2,
          const __half* __restrict__ h2, const float* __restrict__ b2,
          float* __restrict__ out, int N) {
    int w = (blockIdx.x * blockDim.x + threadIdx.x) >> 5;
    if (w >= N) return;
    int lane = threadIdx.x & 31;
    float adn = ad2[w];
    int beg = rowptr[w], end = rowptr[w + 1];

    float4 a = make_float4(0.f, 0.f, 0.f, 0.f);
    float den = 0.f;
    for (int j = beg; j < end; j++) {
        int s = srcs[j];
        float e = as2[s] + adn;
        e = (e > 0.f) ? e : 0.2f * e;
        float wt = __expf(e);
        den += wt;
        uint2 hv = reinterpret_cast<const uint2*>(h2 + (size_t)s * C2T)[lane];
        float2 f0 = __half22float2(*reinterpret_cast<const __half2*>(&hv.x));
        float2 f1 = __half22float2(*reinterpret_cast<const __half2*>(&hv.y));
        a.x += wt * f0.x; a.y += wt * f0.y; a.z += wt * f1.x; a.w += wt * f1.y;
    }
    float inv = 1.f / (den + 1e-16f);
    int c = lane * 4;
    float4 bb = *reinterpret_cast<const float4*>(b2 + c);
    float4 o = make_float4(fmaxf(a.x * inv + bb.x, 0.f),
                           fmaxf(a.y * inv + bb.y, 0.f),
                           fmaxf(a.z * inv + bb.z, 0.f),
                           fmaxf(a.w * inv + bb.w, 0.f));
    reinterpret_cast<float4*>(out + (size_t)w * C2T)[lane] = o;
}

// ---------------- launch -----------------------------------------------------
template <typename T, size_t S>
static T* sym_addr(T (&sym)[S]) {
    void* p = nullptr;
    cudaGetSymbolAddress(&p, sym);   // host API, capture-safe
    return (T*)p;
}

extern "C" void kernel_launch(void* const* d_in, const int* in_sizes, int n_in,
                              void* d_out, int out_size) {
    const float* x        = (const float*)d_in[0];
    const int*   ei       = (const int*)  d_in[1];
    const float* W1       = (const float*)d_in[2];
    const float* att_src1 = (const float*)d_in[3];
    const float* att_dst1 = (const float*)d_in[4];
    const float* b1       = (const float*)d_in[5];
    const float* W2       = (const float*)d_in[6];
    const float* att_src2 = (const float*)d_in[7];
    const float* att_dst2 = (const float*)d_in[8];
    const float* b2       = (const float*)d_in[9];
    float* out = (float*)d_out;

    __half* h1h   = sym_addr(g_h1h);
    __half* hacth = sym_addr(g_hacth);
    __half* h2h   = sym_addr(g_h2h);
    float* as1  = sym_addr(g_as1);
    float* ad1  = sym_addr(g_ad1);
    float* as2  = sym_addr(g_as2);
    float* ad2  = sym_addr(g_ad2);
    int* deg    = sym_addr(g_deg);
    int* pos    = sym_addr(g_pos);
    int* rowptr = sym_addr(g_rowptr);
    int* srcs   = sym_addr(g_srcs);

    int N = in_sizes[0] / EIN;   // 50000
    int E = in_sizes[1] / 2;     // 800000
    int Etot = E + N;

    // ---- CSR build (dst-bucketed edge list) ----
    csr_init   <<<(N + 255) / 256, 256>>>(deg, pos, N);
    csr_count  <<<(E + 255) / 256, 256>>>(ei, deg, E);
    csr_scan   <<<1, 1024>>>(deg, rowptr, N);
    csr_scatter<<<(Etot + 255) / 256, 256>>>(ei, rowptr, pos, srcs, E, N);

    // ---- layer 1 ----
    {
        dim3 grid(C1T / 128, (N + 127) / 128);
        gemm_tf32<EIN, float><<<grid, 256>>>(x, W1, h1h, N, C1T);
    }
    att_dot<<<(N * 4 + 255) / 256, 256>>>(h1h, att_src1, att_dst1, as1, ad1, N, 4, 64);
    agg1<<<((size_t)N * 32 + 255) / 256, 256>>>(rowptr, srcs, as1, ad1, h1h, b1, hacth, N);

    // ---- layer 2 ----
    {
        dim3 grid(C2T / 128, (N + 127) / 128);
        gemm_tf32<C1T, __half><<<grid, 256>>>(hacth, W2, h2h, N, C2T);
    }
    att_dot<<<(N + 255) / 256, 256>>>(h2h, att_src2, att_dst2, as2, ad2, N, 1, 128);
    agg2<<<((size_t)N * 32 + 255) / 256, 256>>>(rowptr, srcs, as2, ad2, h2h, b2, out, N);
}

// round 14
// speedup vs baseline: 2.5647x; 1.1366x over previous
#include <cuda_runtime.h>
#include <cuda_fp16.h>
#include <cstdint>

#define NN   50000
#define EIN  128
#define C1T  256   // H1*C1
#define C2T  128   // H2*C2
#define EMAX 800000
#define ETOT (EMAX + NN)
#define SCAN_TILE 1024
#define SCAN_BLKS ((NN + SCAN_TILE - 1) / SCAN_TILE)

// ---------------- scratch (device globals; allocation is forbidden) ----------
// Only touched through cudaGetSymbolAddress pointers (host-shadow + ATS trap).
__device__ __align__(256) __half g_h1h  [NN * C1T];   // gemm1 out (fp16)
__device__ __align__(256) __half g_hacth[NN * C1T];   // layer2 input (fp16)
__device__ __align__(256) __half g_h2h  [NN * C2T];   // gemm2 out (fp16)
__device__ float g_as1[NN * 4];
__device__ float g_ad1[NN * 4];
__device__ float g_as2[NN];
__device__ float g_ad2[NN];
__device__ int   g_deg[NN];
__device__ int   g_pos[NN];
__device__ int   g_rowptr[NN + 1];
__device__ int   g_srcs[ETOT];
__device__ int   g_bsum[SCAN_BLKS + 1];

// row strides for vectorized gathers
#define H1_U4 (C1T / 8)    // 256 halves / 8 per uint4 = 32  (R13 bug: was 16)
#define H2_U2 (C2T / 4)    // 128 halves / 4 per uint2 = 32

// ---------------- CSR build --------------------------------------------------
__global__ void csr_init(int* __restrict__ deg, int* __restrict__ pos, int N) {
    int i = blockIdx.x * blockDim.x + threadIdx.x;
    if (i < N) { deg[i] = 1; pos[i] = 0; }   // deg starts at 1: self loop
}

__global__ void csr_count(const int* __restrict__ ei, int* __restrict__ deg, int E) {
    int i = blockIdx.x * blockDim.x + threadIdx.x;
    if (i < E) atomicAdd(&deg[ei[E + i]], 1);
}

// ---- 3-phase grid scan: deg -> exclusive rowptr ----
__global__ __launch_bounds__(256)
void scan1(const int* __restrict__ deg, int* __restrict__ rowptr,
           int* __restrict__ bsum, int N) {
    __shared__ int ts[256];
    int t = threadIdx.x;
    int base = blockIdx.x * SCAN_TILE + t * 4;
    int v[4]; int s = 0;
    #pragma unroll
    for (int q = 0; q < 4; q++) {
        v[q] = (base + q < N) ? deg[base + q] : 0;
        s += v[q];
    }
    ts[t] = s;
    __syncthreads();
    #pragma unroll
    for (int off = 1; off < 256; off <<= 1) {
        int u = (t >= off) ? ts[t - off] : 0;
        __syncthreads();
        ts[t] += u;
        __syncthreads();
    }
    int run = (t == 0) ? 0 : ts[t - 1];
    #pragma unroll
    for (int q = 0; q < 4; q++) {
        if (base + q < N) rowptr[base + q] = run;
        run += v[q];
    }
    if (t == 255) bsum[blockIdx.x] = ts[255];
}

__global__ void scan2(int* __restrict__ bsum, int B) {
    if (threadIdx.x == 0 && blockIdx.x == 0) {
        int run = 0;
        for (int b = 0; b < B; b++) { int v = bsum[b]; bsum[b] = run; run += v; }
        bsum[B] = run;
    }
}

__global__ void scan3(int* __restrict__ rowptr, const int* __restrict__ bsum, int N) {
    int i = blockIdx.x * blockDim.x + threadIdx.x;
    if (i < N) rowptr[i] += bsum[i / SCAN_TILE];
    if (i == N) rowptr[N] = bsum[SCAN_BLKS];
}

__global__ void csr_scatter(const int* __restrict__ ei,
                            const int* __restrict__ rowptr, int* __restrict__ pos,
                            int* __restrict__ srcs, int E, int N) {
    int i = blockIdx.x * blockDim.x + threadIdx.x;
    if (i >= E + N) return;
    int src, dst;
    if (i < E) { src = ei[i]; dst = ei[E + i]; }
    else       { src = dst = i - E; }
    int p = atomicAdd(&pos[dst], 1);
    srcs[rowptr[dst] + p] = src;
}

// ---------------- tf32 tensor-core GEMM --------------------------------------
__device__ __forceinline__ uint32_t f2tf32(float x) {
    uint32_t r;
    asm("cvt.rna.tf32.f32 %0, %1;" : "=r"(r) : "f"(x));
    return r;
}

__device__ __forceinline__ void mma_tf32(float* d, const uint32_t* a, const uint32_t* b) {
    asm volatile(
        "mma.sync.aligned.m16n8k8.row.col.f32.tf32.tf32.f32 "
        "{%0,%1,%2,%3}, {%4,%5,%6,%7}, {%8,%9}, {%0,%1,%2,%3};"
        : "+f"(d[0]), "+f"(d[1]), "+f"(d[2]), "+f"(d[3])
        : "r"(a[0]), "r"(a[1]), "r"(a[2]), "r"(a[3]), "r"(b[0]), "r"(b[1]));
}

template <int K, typename AT>
__global__ __launch_bounds__(256)
void gemm_tf32(const AT* __restrict__ A, const float* __restrict__ B,
               __half* __restrict__ C, int M, int Ncols) {
    __shared__ uint32_t As[16][132];   // [k][m], pad -> conflict-free frags
    __shared__ uint32_t Bs[16][132];   // [k][n]
    int tid  = threadIdx.x;
    int wid  = tid >> 5;
    int lane = tid & 31;
    int row0 = blockIdx.y * 128;
    int col0 = blockIdx.x * 128;
    int m0 = (wid >> 2) * 64;
    int n0 = (wid & 3) * 32;
    int rq = lane >> 2;                // 0..7
    int kl = lane & 3;                 // 0..3

    float acc[4][4][4];
    #pragma unroll
    for (int mt = 0; mt < 4; mt++)
        #pragma unroll
        for (int nt = 0; nt < 4; nt++)
            #pragma unroll
            for (int r = 0; r < 4; r++) acc[mt][nt][r] = 0.f;

    for (int k0 = 0; k0 < K; k0 += 16) {
        // ---- stage A: 128 rows x 16 k ----
        float a_f[2][4]; int a_row[2], a_ko[2];
        if (sizeof(AT) == 4) {
            #pragma unroll
            for (int u = 0; u < 2; u++) {
                int l = tid + u * 256;
                a_row[u] = l >> 2;
                a_ko[u]  = (l & 3) * 4;
                int gr = row0 + a_row[u];
                float4 v = (gr < M)
                    ? *reinterpret_cast<const float4*>(
                          (const float*)A + (size_t)gr * K + k0 + a_ko[u])
                    : make_float4(0.f, 0.f, 0.f, 0.f);
                a_f[u][0] = v.x; a_f[u][1] = v.y; a_f[u][2] = v.z; a_f[u][3] = v.w;
            }
        } else {
            a_row[0] = tid >> 1;
            a_ko[0]  = (tid & 1) * 8;
            int gr = row0 + a_row[0];
            uint4 v = (gr < M)
                ? *reinterpret_cast<const uint4*>(
                      (const __half*)A + (size_t)gr * K + k0 + a_ko[0])
                : make_uint4(0u, 0u, 0u, 0u);
            const __half2* hp = reinterpret_cast<const __half2*>(&v);
            #pragma unroll
            for (int j = 0; j < 4; j++) {
                float2 f = __half22float2(hp[j]);
                a_f[j >> 1][(j & 1) * 2 + 0] = f.x;
                a_f[j >> 1][(j & 1) * 2 + 1] = f.y;
            }
        }
        // ---- stage B: 16 k x 128 n (fp32 weights) ----
        float4 bv[2]; int brow[2], bc4[2];
        #pragma unroll
        for (int u = 0; u < 2; u++) {
            int l = tid + u * 256;
            brow[u] = l >> 5;
            bc4[u]  = l & 31;
            bv[u] = *reinterpret_cast<const float4*>(
                B + (size_t)(k0 + brow[u]) * Ncols + col0 + bc4[u] * 4);
        }
        __syncthreads();   // previous stage fully consumed
        if (sizeof(AT) == 4) {
            #pragma unroll
            for (int u = 0; u < 2; u++)
                #pragma unroll
                for (int j = 0; j < 4; j++)
                    As[a_ko[u] + j][a_row[u]] = f2tf32(a_f[u][j]);
        } else {
            #pragma unroll
            for (int j = 0; j < 8; j++)
                As[a_ko[0] + j][a_row[0]] = f2tf32(a_f[j >> 2][j & 3]);
        }
        #pragma unroll
        for (int u = 0; u < 2; u++) {
            uint32_t* bp = &Bs[brow[u]][bc4[u] * 4];
            bp[0] = f2tf32(bv[u].x); bp[1] = f2tf32(bv[u].y);
            bp[2] = f2tf32(bv[u].z); bp[3] = f2tf32(bv[u].w);
        }
        __syncthreads();

        #pragma unroll
        for (int k8 = 0; k8 < 16; k8 += 8) {
            int kq = k8 + kl;
            uint32_t af[4][4], bf[4][2];
            #pragma unroll
            for (int mt = 0; mt < 4; mt++) {
                int r = m0 + mt * 16 + rq;
                af[mt][0] = As[kq][r];     af[mt][1] = As[kq][r + 8];
                af[mt][2] = As[kq + 4][r]; af[mt][3] = As[kq + 4][r + 8];
            }
            #pragma unroll
            for (int nt = 0; nt < 4; nt++) {
                int c = n0 + nt * 8 + rq;
                bf[nt][0] = Bs[kq][c];
                bf[nt][1] = Bs[kq + 4][c];
            }
            #pragma unroll
            for (int mt = 0; mt < 4; mt++)
                #pragma unroll
                for (int nt = 0; nt < 4; nt++)
                    mma_tf32(acc[mt][nt], af[mt], bf[nt]);
        }
    }

    // epilogue: fp16 output, per-thread half2 fragments
    #pragma unroll
    for (int mt = 0; mt < 4; mt++) {
        int r_lo = row0 + m0 + mt * 16 + rq;
        int r_hi = r_lo + 8;
        #pragma unroll
        for (int nt = 0; nt < 4; nt++) {
            int c = col0 + n0 + nt * 8 + 2 * kl;
            if (r_lo < M)
                *reinterpret_cast<__half2*>(C + (size_t)r_lo * Ncols + c) =
                    __floats2half2_rn(acc[mt][nt][0], acc[mt][nt][1]);
            if (r_hi < M)
                *reinterpret_cast<__half2*>(C + (size_t)r_hi * Ncols + c) =
                    __floats2half2_rn(acc[mt][nt][2], acc[mt][nt][3]);
        }
    }
}

// ---------------- attention coefficients (fp16 features, fp32 math) ---------
__global__ void att_dot(const __half* __restrict__ h,
                        const float* __restrict__ atts,
                        const float* __restrict__ attd,
                        float* __restrict__ as_, float* __restrict__ ad_,
                        int N, int H, int C) {
    int i = blockIdx.x * blockDim.x + threadIdx.x;
    if (i >= N * H) return;
    int hh = i % H;
    const __half2* hp = reinterpret_cast<const __half2*>(h + (size_t)i * C);
    const float* sp = atts + hh * C;
    const float* dp = attd + hh * C;
    float s = 0.f, d = 0.f;
    for (int c = 0; c < C / 2; c++) {
        float2 v = __half22float2(hp[c]);
        s += v.x * sp[2 * c] + v.y * sp[2 * c + 1];
        d += v.x * dp[2 * c] + v.y * dp[2 * c + 1];
    }
    as_[i] = s;
    ad_[i] = d;
}

// ---------------- aggregation helpers ----------------------------------------
__device__ __forceinline__ float lrelu_exp(float e) {
    e = (e > 0.f) ? e : 0.2f * e;
    return __expf(e);                   // softmax shift-invariant: no max pass
}

__device__ __forceinline__ void acc8(float* a, const uint4& hv, float wt) {
    const __half2* hp = reinterpret_cast<const __half2*>(&hv);
    #pragma unroll
    for (int q = 0; q < 4; q++) {
        float2 f = __half22float2(hp[q]);
        a[2 * q]     += wt * f.x;
        a[2 * q + 1] += wt * f.y;
    }
}

__device__ __forceinline__ void acc4(float4& a, const uint2& hv, float wt) {
    float2 f0 = __half22float2(*reinterpret_cast<const __half2*>(&hv.x));
    float2 f1 = __half22float2(*reinterpret_cast<const __half2*>(&hv.y));
    a.x += wt * f0.x; a.y += wt * f0.y; a.z += wt * f1.x; a.w += wt * f1.y;
}

// ---------------- layer1 aggregation: warp per dst node, 4-edge unroll -------
// 4 heads x 64ch fp16 messages. Lane: 8 channels (one uint4) of head lane>>3.
// Batch loads (4 idx, 4 att, 4 rows) issued before use -> MLP ~8.
__global__ __launch_bounds__(256)
void agg1(const int* __restrict__ rowptr, const int* __restrict__ srcs,
          const float* __restrict__ as1, const float* __restrict__ ad1,
          const __half* __restrict__ h1, const float* __restrict__ b1,
          __half* __restrict__ hact, int N) {
    int w = (blockIdx.x * blockDim.x + threadIdx.x) >> 5;
    if (w >= N) return;
    int lane = threadIdx.x & 31;
    int head = lane >> 3;
    float adn = ad1[w * 4 + head];
    int beg = rowptr[w], end = rowptr[w + 1];

    const uint4* hb = reinterpret_cast<const uint4*>(h1);
    float a[8] = {0.f, 0.f, 0.f, 0.f, 0.f, 0.f, 0.f, 0.f};
    float den = 0.f;
    int j = beg;
    for (; j + 4 <= end; j += 4) {
        int s0 = srcs[j], s1 = srcs[j + 1], s2 = srcs[j + 2], s3 = srcs[j + 3];
        float e0 = as1[s0 * 4 + head];
        float e1 = as1[s1 * 4 + head];
        float e2 = as1[s2 * 4 + head];
        float e3 = as1[s3 * 4 + head];
        uint4 v0 = hb[(size_t)s0 * H1_U4 + lane];
        uint4 v1 = hb[(size_t)s1 * H1_U4 + lane];
        uint4 v2 = hb[(size_t)s2 * H1_U4 + lane];
        uint4 v3 = hb[(size_t)s3 * H1_U4 + lane];
        float w0 = lrelu_exp(e0 + adn);
        float w1 = lrelu_exp(e1 + adn);
        float w2 = lrelu_exp(e2 + adn);
        float w3 = lrelu_exp(e3 + adn);
        den += (w0 + w1) + (w2 + w3);
        acc8(a, v0, w0); acc8(a, v1, w1); acc8(a, v2, w2); acc8(a, v3, w3);
    }
    for (; j < end; j++) {
        int s = srcs[j];
        float wt = lrelu_exp(as1[s * 4 + head] + adn);
        den += wt;
        uint4 v = hb[(size_t)s * H1_U4 + lane];
        acc8(a, v, wt);
    }
    float inv = 1.f / (den + 1e-16f);
    int c = lane * 8;
    __half2 o[4];
    #pragma unroll
    for (int q = 0; q < 4; q++) {
        float ox = fmaxf(a[2 * q]     * inv + b1[c + 2 * q],     0.f);
        float oy = fmaxf(a[2 * q + 1] * inv + b1[c + 2 * q + 1], 0.f);
        o[q] = __floats2half2_rn(ox, oy);
    }
    reinterpret_cast<uint4*>(hact + (size_t)w * C1T)[lane] =
        *reinterpret_cast<const uint4*>(o);
}

// ---------------- layer2 aggregation: warp per dst node, 4-edge unroll -------
__global__ __launch_bounds__(256)
void agg2(const int* __restrict__ rowptr, const int* __restrict__ srcs,
          const float* __restrict__ as2, const float* __restrict__ ad2,
          const __half* __restrict__ h2, const float* __restrict__ b2,
          float* __restrict__ out, int N) {
    int w = (blockIdx.x * blockDim.x + threadIdx.x) >> 5;
    if (w >= N) return;
    int lane = threadIdx.x & 31;
    float adn = ad2[w];
    int beg = rowptr[w], end = rowptr[w + 1];

    const uint2* hb = reinterpret_cast<const uint2*>(h2);
    float4 a = make_float4(0.f, 0.f, 0.f, 0.f);
    float den = 0.f;
    int j = beg;
    for (; j + 4 <= end; j += 4) {
        int s0 = srcs[j], s1 = srcs[j + 1], s2 = srcs[j + 2], s3 = srcs[j + 3];
        float e0 = as2[s0], e1 = as2[s1], e2 = as2[s2], e3 = as2[s3];
        uint2 v0 = hb[(size_t)s0 * H2_U2 + lane];
        uint2 v1 = hb[(size_t)s1 * H2_U2 + lane];
        uint2 v2 = hb[(size_t)s2 * H2_U2 + lane];
        uint2 v3 = hb[(size_t)s3 * H2_U2 + lane];
        float w0 = lrelu_exp(e0 + adn);
        float w1 = lrelu_exp(e1 + adn);
        float w2 = lrelu_exp(e2 + adn);
        float w3 = lrelu_exp(e3 + adn);
        den += (w0 + w1) + (w2 + w3);
        acc4(a, v0, w0); acc4(a, v1, w1); acc4(a, v2, w2); acc4(a, v3, w3);
    }
    for (; j < end; j++) {
        int s = srcs[j];
        float wt = lrelu_exp(as2[s] + adn);
        den += wt;
        uint2 v = hb[(size_t)s * H2_U2 + lane];
        acc4(a, v, wt);
    }
    float inv = 1.f / (den + 1e-16f);
    int c = lane * 4;
    float4 bb = *reinterpret_cast<const float4*>(b2 + c);
    float4 o = make_float4(fmaxf(a.x * inv + bb.x, 0.f),
                           fmaxf(a.y * inv + bb.y, 0.f),
                           fmaxf(a.z * inv + bb.z, 0.f),
                           fmaxf(a.w * inv + bb.w, 0.f));
    reinterpret_cast<float4*>(out + (size_t)w * C2T)[lane] = o;
}

// ---------------- launch -----------------------------------------------------
template <typename T, size_t S>
static T* sym_addr(T (&sym)[S]) {
    void* p = nullptr;
    cudaGetSymbolAddress(&p, sym);   // host API, capture-safe
    return (T*)p;
}

extern "C" void kernel_launch(void* const* d_in, const int* in_sizes, int n_in,
                              void* d_out, int out_size) {
    const float* x        = (const float*)d_in[0];
    const int*   ei       = (const int*)  d_in[1];
    const float* W1       = (const float*)d_in[2];
    const float* att_src1 = (const float*)d_in[3];
    const float* att_dst1 = (const float*)d_in[4];
    const float* b1       = (const float*)d_in[5];
    const float* W2       = (const float*)d_in[6];
    const float* att_src2 = (const float*)d_in[7];
    const float* att_dst2 = (const float*)d_in[8];
    const float* b2       = (const float*)d_in[9];
    float* out = (float*)d_out;

    __half* h1h   = sym_addr(g_h1h);
    __half* hacth = sym_addr(g_hacth);
    __half* h2h   = sym_addr(g_h2h);
    float* as1  = sym_addr(g_as1);
    float* ad1  = sym_addr(g_ad1);
    float* as2  = sym_addr(g_as2);
    float* ad2  = sym_addr(g_ad2);
    int* deg    = sym_addr(g_deg);
    int* pos    = sym_addr(g_pos);
    int* rowptr = sym_addr(g_rowptr);
    int* srcs   = sym_addr(g_srcs);
    int* bsum   = sym_addr(g_bsum);

    int N = in_sizes[0] / EIN;   // 50000
    int E = in_sizes[1] / 2;     // 800000
    int Etot = E + N;

    // ---- CSR build (dst-bucketed edge list) ----
    csr_init   <<<(N + 255) / 256, 256>>>(deg, pos, N);
    csr_count  <<<(E + 255) / 256, 256>>>(ei, deg, E);
    scan1      <<<SCAN_BLKS, 256>>>(deg, rowptr, bsum, N);
    scan2      <<<1, 32>>>(bsum, SCAN_BLKS);
    scan3      <<<(N + 256) / 256, 256>>>(rowptr, bsum, N);
    csr_scatter<<<(Etot + 255) / 256, 256>>>(ei, rowptr, pos, srcs, E, N);

    // ---- layer 1 ----
    {
        dim3 grid(C1T / 128, (N + 127) / 128);
        gemm_tf32<EIN, float><<<grid, 256>>>(x, W1, h1h, N, C1T);
    }
    att_dot<<<(N * 4 + 255) / 256, 256>>>(h1h, att_src1, att_dst1, as1, ad1, N, 4, 64);
    agg1<<<((size_t)N * 32 + 255) / 256, 256>>>(rowptr, srcs, as1, ad1, h1h, b1, hacth, N);

    // ---- layer 2 ----
    {
        dim3 grid(C2T / 128, (N + 127) / 128);
        gemm_tf32<C1T, __half><<<grid, 256>>>(hacth, W2, h2h, N, C2T);
    }
    att_dot<<<(N + 255) / 256, 256>>>(h2h, att_src2, att_dst2, as2, ad2, N, 1, 128);
    agg2<<<((size_t)N * 32 + 255) / 256, 256>>>(rowptr, srcs, as2, ad2, h2h, b2, out, N);
}

// round 15
// speedup vs baseline: 2.7170x; 1.0594x over previous
#include <cuda_runtime.h>
#include <cuda_fp16.h>
#include <cstdint>

#define NN   50000
#define EIN  128
#define C1T  256   // H1*C1
#define C2T  128   // H2*C2
#define EMAX 800000
#define ETOT (EMAX + NN)
#define SCAN_TILE 1024
#define SCAN_BLKS ((NN + SCAN_TILE - 1) / SCAN_TILE)

// ---------------- scratch (device globals; allocation is forbidden) ----------
// Only touched through cudaGetSymbolAddress pointers (host-shadow + ATS trap).
__device__ __align__(256) __half g_h1h  [NN * C1T];   // gemm1 out (fp16)
__device__ __align__(256) __half g_hacth[NN * C1T];   // layer2 input (fp16)
__device__ __align__(256) __half g_h2h  [NN * C2T];   // gemm2 out (fp16)
__device__ float g_as1[NN * 4];
__device__ float g_ad1[NN * 4];
__device__ float g_as2[NN];
__device__ float g_ad2[NN];
__device__ int   g_deg[NN];
__device__ int   g_pos[NN];
__device__ int   g_rowptr[NN + 1];
__device__ int   g_srcs[ETOT];
__device__ int   g_bsum[SCAN_BLKS + 1];

// row strides for vectorized gathers
#define H1_U4 (C1T / 8)    // 256 halves / 8 per uint4 = 32
#define H2_U2 (C2T / 4)    // 128 halves / 4 per uint2 = 32

// ---------------- CSR build --------------------------------------------------
__global__ void csr_init(int* __restrict__ deg, int* __restrict__ pos, int N) {
    int i = blockIdx.x * blockDim.x + threadIdx.x;
    if (i < N) { deg[i] = 1; pos[i] = 0; }   // deg starts at 1: self loop
}

__global__ void csr_count(const int* __restrict__ ei, int* __restrict__ deg, int E) {
    int i = blockIdx.x * blockDim.x + threadIdx.x;
    if (i < E) atomicAdd(&deg[ei[E + i]], 1);
}

// ---- scan phase 1: per-block (1024 items) local exclusive scan + block sum --
__global__ __launch_bounds__(256)
void scan1(const int* __restrict__ deg, int* __restrict__ rowptr,
           int* __restrict__ bsum, int N) {
    __shared__ int ts[256];
    int t = threadIdx.x;
    int base = blockIdx.x * SCAN_TILE + t * 4;
    int v[4]; int s = 0;
    #pragma unroll
    for (int q = 0; q < 4; q++) {
        v[q] = (base + q < N) ? deg[base + q] : 0;
        s += v[q];
    }
    ts[t] = s;
    __syncthreads();
    #pragma unroll
    for (int off = 1; off < 256; off <<= 1) {
        int u = (t >= off) ? ts[t - off] : 0;
        __syncthreads();
        ts[t] += u;
        __syncthreads();
    }
    int run = (t == 0) ? 0 : ts[t - 1];
    #pragma unroll
    for (int q = 0; q < 4; q++) {
        if (base + q < N) rowptr[base + q] = run;
        run += v[q];
    }
    if (t == 255) bsum[blockIdx.x] = ts[255];
}

// ---- scan phases 2+3 fused: every block re-scans the 49 block sums (cheap,
// parallel Hillis-Steele in shared) and applies its offset. Kills the tiny
// serial scan2 launch (4.7us of pure launch+latency overhead in R14 ncu). ----
__global__ __launch_bounds__(256)
void scan23(int* __restrict__ rowptr, const int* __restrict__ bsum, int N) {
    __shared__ int ts[64];
    int t = threadIdx.x;
    if (t < 64) ts[t] = (t < SCAN_BLKS) ? bsum[t] : 0;
    __syncthreads();
    #pragma unroll
    for (int off = 1; off < 64; off <<= 1) {
        int u = (t < 64 && t >= off) ? ts[t - off] : 0;
        __syncthreads();
        if (t < 64) ts[t] += u;
        __syncthreads();
    }
    // inclusive scan: exclusive offset for tile b is ts[b-1] (0 for b=0)
    int i = blockIdx.x * blockDim.x + t;
    if (i < N) {
        int blk = i / SCAN_TILE;
        if (blk > 0) rowptr[i] += ts[blk - 1];
    }
    if (i == N) rowptr[N] = ts[SCAN_BLKS - 1];
}

__global__ void csr_scatter(const int* __restrict__ ei,
                            const int* __restrict__ rowptr, int* __restrict__ pos,
                            int* __restrict__ srcs, int E, int N) {
    int i = blockIdx.x * blockDim.x + threadIdx.x;
    if (i >= E + N) return;
    int src, dst;
    if (i < E) { src = ei[i]; dst = ei[E + i]; }
    else       { src = dst = i - E; }
    int p = atomicAdd(&pos[dst], 1);
    srcs[rowptr[dst] + p] = src;
}

// ---------------- tf32 tensor-core GEMM --------------------------------------
__device__ __forceinline__ uint32_t f2tf32(float x) {
    uint32_t r;
    asm("cvt.rna.tf32.f32 %0, %1;" : "=r"(r) : "f"(x));
    return r;
}

__device__ __forceinline__ void mma_tf32(float* d, const uint32_t* a, const uint32_t* b) {
    asm volatile(
        "mma.sync.aligned.m16n8k8.row.col.f32.tf32.tf32.f32 "
        "{%0,%1,%2,%3}, {%4,%5,%6,%7}, {%8,%9}, {%0,%1,%2,%3};"
        : "+f"(d[0]), "+f"(d[1]), "+f"(d[2]), "+f"(d[3])
        : "r"(a[0]), "r"(a[1]), "r"(a[2]), "r"(a[3]), "r"(b[0]), "r"(b[1]));
}

template <int K, typename AT>
__global__ __launch_bounds__(256)
void gemm_tf32(const AT* __restrict__ A, const float* __restrict__ B,
               __half* __restrict__ C, int M, int Ncols) {
    __shared__ uint32_t As[16][132];   // [k][m], pad -> conflict-free frags
    __shared__ uint32_t Bs[16][132];   // [k][n]
    int tid  = threadIdx.x;
    int wid  = tid >> 5;
    int lane = tid & 31;
    int row0 = blockIdx.y * 128;
    int col0 = blockIdx.x * 128;
    int m0 = (wid >> 2) * 64;
    int n0 = (wid & 3) * 32;
    int rq = lane >> 2;                // 0..7
    int kl = lane & 3;                 // 0..3

    float acc[4][4][4];
    #pragma unroll
    for (int mt = 0; mt < 4; mt++)
        #pragma unroll
        for (int nt = 0; nt < 4; nt++)
            #pragma unroll
            for (int r = 0; r < 4; r++) acc[mt][nt][r] = 0.f;

    for (int k0 = 0; k0 < K; k0 += 16) {
        // ---- stage A: 128 rows x 16 k ----
        float a_f[2][4]; int a_row[2], a_ko[2];
        if (sizeof(AT) == 4) {
            #pragma unroll
            for (int u = 0; u < 2; u++) {
                int l = tid + u * 256;
                a_row[u] = l >> 2;
                a_ko[u]  = (l & 3) * 4;
                int gr = row0 + a_row[u];
                float4 v = (gr < M)
                    ? *reinterpret_cast<const float4*>(
                          (const float*)A + (size_t)gr * K + k0 + a_ko[u])
                    : make_float4(0.f, 0.f, 0.f, 0.f);
                a_f[u][0] = v.x; a_f[u][1] = v.y; a_f[u][2] = v.z; a_f[u][3] = v.w;
            }
        } else {
            a_row[0] = tid >> 1;
            a_ko[0]  = (tid & 1) * 8;
            int gr = row0 + a_row[0];
            uint4 v = (gr < M)
                ? *reinterpret_cast<const uint4*>(
                      (const __half*)A + (size_t)gr * K + k0 + a_ko[0])
                : make_uint4(0u, 0u, 0u, 0u);
            const __half2* hp = reinterpret_cast<const __half2*>(&v);
            #pragma unroll
            for (int j = 0; j < 4; j++) {
                float2 f = __half22float2(hp[j]);
                a_f[j >> 1][(j & 1) * 2 + 0] = f.x;
                a_f[j >> 1][(j & 1) * 2 + 1] = f.y;
            }
        }
        // ---- stage B: 16 k x 128 n (fp32 weights) ----
        float4 bv[2]; int brow[2], bc4[2];
        #pragma unroll
        for (int u = 0; u < 2; u++) {
            int l = tid + u * 256;
            brow[u] = l >> 5;
            bc4[u]  = l & 31;
            bv[u] = *reinterpret_cast<const float4*>(
                B + (size_t)(k0 + brow[u]) * Ncols + col0 + bc4[u] * 4);
        }
        __syncthreads();   // previous stage fully consumed
        if (sizeof(AT) == 4) {
            #pragma unroll
            for (int u = 0; u < 2; u++)
                #pragma unroll
                for (int j = 0; j < 4; j++)
                    As[a_ko[u] + j][a_row[u]] = f2tf32(a_f[u][j]);
        } else {
            #pragma unroll
            for (int j = 0; j < 8; j++)
                As[a_ko[0] + j][a_row[0]] = f2tf32(a_f[j >> 2][j & 3]);
        }
        #pragma unroll
        for (int u = 0; u < 2; u++) {
            uint32_t* bp = &Bs[brow[u]][bc4[u] * 4];
            bp[0] = f2tf32(bv[u].x); bp[1] = f2tf32(bv[u].y);
            bp[2] = f2tf32(bv[u].z); bp[3] = f2tf32(bv[u].w);
        }
        __syncthreads();

        #pragma unroll
        for (int k8 = 0; k8 < 16; k8 += 8) {
            int kq = k8 + kl;
            uint32_t af[4][4], bf[4][2];
            #pragma unroll
            for (int mt = 0; mt < 4; mt++) {
                int r = m0 + mt * 16 + rq;
                af[mt][0] = As[kq][r];     af[mt][1] = As[kq][r + 8];
                af[mt][2] = As[kq + 4][r]; af[mt][3] = As[kq + 4][r + 8];
            }
            #pragma unroll
            for (int nt = 0; nt < 4; nt++) {
                int c = n0 + nt * 8 + rq;
                bf[nt][0] = Bs[kq][c];
                bf[nt][1] = Bs[kq + 4][c];
            }
            #pragma unroll
            for (int mt = 0; mt < 4; mt++)
                #pragma unroll
                for (int nt = 0; nt < 4; nt++)
                    mma_tf32(acc[mt][nt], af[mt], bf[nt]);
        }
    }

    // epilogue: fp16 output, per-thread half2 fragments
    #pragma unroll
    for (int mt = 0; mt < 4; mt++) {
        int r_lo = row0 + m0 + mt * 16 + rq;
        int r_hi = r_lo + 8;
        #pragma unroll
        for (int nt = 0; nt < 4; nt++) {
            int c = col0 + n0 + nt * 8 + 2 * kl;
            if (r_lo < M)
                *reinterpret_cast<__half2*>(C + (size_t)r_lo * Ncols + c) =
                    __floats2half2_rn(acc[mt][nt][0], acc[mt][nt][1]);
            if (r_hi < M)
                *reinterpret_cast<__half2*>(C + (size_t)r_hi * Ncols + c) =
                    __floats2half2_rn(acc[mt][nt][2], acc[mt][nt][3]);
        }
    }
}

// ---------------- attention coefficients (fp16 features, fp32 math) ---------
__global__ void att_dot(const __half* __restrict__ h,
                        const float* __restrict__ atts,
                        const float* __restrict__ attd,
                        float* __restrict__ as_, float* __restrict__ ad_,
                        int N, int H, int C) {
    int i = blockIdx.x * blockDim.x + threadIdx.x;
    if (i >= N * H) return;
    int hh = i % H;
    const __half2* hp = reinterpret_cast<const __half2*>(h + (size_t)i * C);
    const float* sp = atts + hh * C;
    const float* dp = attd + hh * C;
    float s = 0.f, d = 0.f;
    for (int c = 0; c < C / 2; c++) {
        float2 v = __half22float2(hp[c]);
        s += v.x * sp[2 * c] + v.y * sp[2 * c + 1];
        d += v.x * dp[2 * c] + v.y * dp[2 * c + 1];
    }
    as_[i] = s;
    ad_[i] = d;
}

// ---------------- aggregation helpers ----------------------------------------
__device__ __forceinline__ float lrelu_exp(float e) {
    e = (e > 0.f) ? e : 0.2f * e;
    return __expf(e);                   // softmax shift-invariant: no max pass
}

__device__ __forceinline__ void acc8(float* a, const uint4& hv, float wt) {
    const __half2* hp = reinterpret_cast<const __half2*>(&hv);
    #pragma unroll
    for (int q = 0; q < 4; q++) {
        float2 f = __half22float2(hp[q]);
        a[2 * q]     += wt * f.x;
        a[2 * q + 1] += wt * f.y;
    }
}

__device__ __forceinline__ void acc4(float4& a, const uint2& hv, float wt) {
    float2 f0 = __half22float2(*reinterpret_cast<const __half2*>(&hv.x));
    float2 f1 = __half22float2(*reinterpret_cast<const __half2*>(&hv.y));
    a.x += wt * f0.x; a.y += wt * f0.y; a.z += wt * f1.x; a.w += wt * f1.y;
}

// ---------------- layer1 aggregation: warp per dst node, 4-edge unroll -------
__global__ __launch_bounds__(256)
void agg1(const int* __restrict__ rowptr, const int* __restrict__ srcs,
          const float* __restrict__ as1, const float* __restrict__ ad1,
          const __half* __restrict__ h1, const float* __restrict__ b1,
          __half* __restrict__ hact, int N) {
    int w = (blockIdx.x * blockDim.x + threadIdx.x) >> 5;
    if (w >= N) return;
    int lane = threadIdx.x & 31;
    int head = lane >> 3;
    float adn = ad1[w * 4 + head];
    int beg = rowptr[w], end = rowptr[w + 1];

    const uint4* hb = reinterpret_cast<const uint4*>(h1);
    float a[8] = {0.f, 0.f, 0.f, 0.f, 0.f, 0.f, 0.f, 0.f};
    float den = 0.f;
    int j = beg;
    for (; j + 4 <= end; j += 4) {
        int s0 = srcs[j], s1 = srcs[j + 1], s2 = srcs[j + 2], s3 = srcs[j + 3];
        float e0 = as1[s0 * 4 + head];
        float e1 = as1[s1 * 4 + head];
        float e2 = as1[s2 * 4 + head];
        float e3 = as1[s3 * 4 + head];
        uint4 v0 = hb[(size_t)s0 * H1_U4 + lane];
        uint4 v1 = hb[(size_t)s1 * H1_U4 + lane];
        uint4 v2 = hb[(size_t)s2 * H1_U4 + lane];
        uint4 v3 = hb[(size_t)s3 * H1_U4 + lane];
        float w0 = lrelu_exp(e0 + adn);
        float w1 = lrelu_exp(e1 + adn);
        float w2 = lrelu_exp(e2 + adn);
        float w3 = lrelu_exp(e3 + adn);
        den += (w0 + w1) + (w2 + w3);
        acc8(a, v0, w0); acc8(a, v1, w1); acc8(a, v2, w2); acc8(a, v3, w3);
    }
    for (; j < end; j++) {
        int s = srcs[j];
        float wt = lrelu_exp(as1[s * 4 + head] + adn);
        den += wt;
        uint4 v = hb[(size_t)s * H1_U4 + lane];
        acc8(a, v, wt);
    }
    float inv = 1.f / (den + 1e-16f);
    int c = lane * 8;
    __half2 o[4];
    #pragma unroll
    for (int q = 0; q < 4; q++) {
        float ox = fmaxf(a[2 * q]     * inv + b1[c + 2 * q],     0.f);
        float oy = fmaxf(a[2 * q + 1] * inv + b1[c + 2 * q + 1], 0.f);
        o[q] = __floats2half2_rn(ox, oy);
    }
    reinterpret_cast<uint4*>(hact + (size_t)w * C1T)[lane] =
        *reinterpret_cast<const uint4*>(o);
}

// ---------------- layer2 aggregation: warp per dst node, 4-edge unroll -------
__global__ __launch_bounds__(256)
void agg2(const int* __restrict__ rowptr, const int* __restrict__ srcs,
          const float* __restrict__ as2, const float* __restrict__ ad2,
          const __half* __restrict__ h2, const float* __restrict__ b2,
          float* __restrict__ out, int N) {
    int w = (blockIdx.x * blockDim.x + threadIdx.x) >> 5;
    if (w >= N) return;
    int lane = threadIdx.x & 31;
    float adn = ad2[w];
    int beg = rowptr[w], end = rowptr[w + 1];

    const uint2* hb = reinterpret_cast<const uint2*>(h2);
    float4 a = make_float4(0.f, 0.f, 0.f, 0.f);
    float den = 0.f;
    int j = beg;
    for (; j + 4 <= end; j += 4) {
        int s0 = srcs[j], s1 = srcs[j + 1], s2 = srcs[j + 2], s3 = srcs[j + 3];
        float e0 = as2[s0], e1 = as2[s1], e2 = as2[s2], e3 = as2[s3];
        uint2 v0 = hb[(size_t)s0 * H2_U2 + lane];
        uint2 v1 = hb[(size_t)s1 * H2_U2 + lane];
        uint2 v2 = hb[(size_t)s2 * H2_U2 + lane];
        uint2 v3 = hb[(size_t)s3 * H2_U2 + lane];
        float w0 = lrelu_exp(e0 + adn);
        float w1 = lrelu_exp(e1 + adn);
        float w2 = lrelu_exp(e2 + adn);
        float w3 = lrelu_exp(e3 + adn);
        den += (w0 + w1) + (w2 + w3);
        acc4(a, v0, w0); acc4(a, v1, w1); acc4(a, v2, w2); acc4(a, v3, w3);
    }
    for (; j < end; j++) {
        int s = srcs[j];
        float wt = lrelu_exp(as2[s] + adn);
        den += wt;
        uint2 v = hb[(size_t)s * H2_U2 + lane];
        acc4(a, v, wt);
    }
    float inv = 1.f / (den + 1e-16f);
    int c = lane * 4;
    float4 bb = *reinterpret_cast<const float4*>(b2 + c);
    float4 o = make_float4(fmaxf(a.x * inv + bb.x, 0.f),
                           fmaxf(a.y * inv + bb.y, 0.f),
                           fmaxf(a.z * inv + bb.z, 0.f),
                           fmaxf(a.w * inv + bb.w, 0.f));
    reinterpret_cast<float4*>(out + (size_t)w * C2T)[lane] = o;
}

// ---------------- launch -----------------------------------------------------
template <typename T, size_t S>
static T* sym_addr(T (&sym)[S]) {
    void* p = nullptr;
    cudaGetSymbolAddress(&p, sym);   // host API, capture-safe
    return (T*)p;
}

// Side stream + fork/join events. Created on FIRST call (the uncaptured
// correctness run), persisted across calls: destroying a stream that
// participates in an active capture would invalidate the capture. No device
// memory is involved; per-call work is identical and deterministic.
struct StreamCtx {
    cudaStream_t s2;
    cudaEvent_t fork, join;
    StreamCtx() {
        cudaStreamCreateWithFlags(&s2, cudaStreamNonBlocking);
        cudaEventCreateWithFlags(&fork, cudaEventDisableTiming);
        cudaEventCreateWithFlags(&join, cudaEventDisableTiming);
    }
};

extern "C" void kernel_launch(void* const* d_in, const int* in_sizes, int n_in,
                              void* d_out, int out_size) {
    static StreamCtx ctx;   // constructed on first (correctness) call

    const float* x        = (const float*)d_in[0];
    const int*   ei       = (const int*)  d_in[1];
    const float* W1       = (const float*)d_in[2];
    const float* att_src1 = (const float*)d_in[3];
    const float* att_dst1 = (const float*)d_in[4];
    const float* b1       = (const float*)d_in[5];
    const float* W2       = (const float*)d_in[6];
    const float* att_src2 = (const float*)d_in[7];
    const float* att_dst2 = (const float*)d_in[8];
    const float* b2       = (const float*)d_in[9];
    float* out = (float*)d_out;

    __half* h1h   = sym_addr(g_h1h);
    __half* hacth = sym_addr(g_hacth);
    __half* h2h   = sym_addr(g_h2h);
    float* as1  = sym_addr(g_as1);
    float* ad1  = sym_addr(g_ad1);
    float* as2  = sym_addr(g_as2);
    float* ad2  = sym_addr(g_ad2);
    int* deg    = sym_addr(g_deg);
    int* pos    = sym_addr(g_pos);
    int* rowptr = sym_addr(g_rowptr);
    int* srcs   = sym_addr(g_srcs);
    int* bsum   = sym_addr(g_bsum);

    int N = in_sizes[0] / EIN;   // 50000
    int E = in_sizes[1] / 2;     // 800000
    int Etot = E + N;

    // ---- fork: CSR build (independent of gemm1/att_dot1) on side stream ----
    cudaEventRecord(ctx.fork, 0);
    cudaStreamWaitEvent(ctx.s2, ctx.fork, 0);

    csr_init   <<<(N + 255) / 256, 256, 0, ctx.s2>>>(deg, pos, N);
    csr_count  <<<(E + 255) / 256, 256, 0, ctx.s2>>>(ei, deg, E);
    scan1      <<<SCAN_BLKS, 256, 0, ctx.s2>>>(deg, rowptr, bsum, N);
    scan23     <<<(N + 256) / 256, 256, 0, ctx.s2>>>(rowptr, bsum, N);
    csr_scatter<<<(Etot + 255) / 256, 256, 0, ctx.s2>>>(ei, rowptr, pos, srcs, E, N);
    cudaEventRecord(ctx.join, ctx.s2);

    // ---- main stream: layer-1 linear + attention coefficients (overlapped) --
    {
        dim3 grid(C1T / 128, (N + 127) / 128);
        gemm_tf32<EIN, float><<<grid, 256>>>(x, W1, h1h, N, C1T);
    }
    att_dot<<<(N * 4 + 255) / 256, 256>>>(h1h, att_src1, att_dst1, as1, ad1, N, 4, 64);

    // ---- join: agg1 needs BOTH the CSR and the attention coefficients ------
    cudaStreamWaitEvent(0, ctx.join, 0);
    agg1<<<((size_t)N * 32 + 255) / 256, 256>>>(rowptr, srcs, as1, ad1, h1h, b1, hacth, N);

    // ---- layer 2 ----
    {
        dim3 grid(C2T / 128, (N + 127) / 128);
        gemm_tf32<C1T, __half><<<grid, 256>>>(hacth, W2, h2h, N, C2T);
    }
    att_dot<<<(N + 255) / 256, 256>>>(h2h, att_src2, att_dst2, as2, ad2, N, 1, 128);
    agg2<<<((size_t)N * 32 + 255) / 256, 256>>>(rowptr, srcs, as2, ad2, h2h, b2, out, N);
}

// round 16
// speedup vs baseline: 2.8941x; 1.0652x over previous
#include <cuda_runtime.h>
#include <cuda_fp16.h>
#include <cstdint>

#define NN   50000
#define EIN  128
#define C1T  256   // H1*C1
#define C2T  128   // H2*C2
#define EMAX 800000
#define ETOT (EMAX + NN)
#define SCAN_TILE 1024
#define SCAN_BLKS ((NN + SCAN_TILE - 1) / SCAN_TILE)

// ---------------- scratch (device globals; allocation is forbidden) ----------
// Only touched through cudaGetSymbolAddress pointers (host-shadow + ATS trap).
__device__ __align__(256) __half g_h1h  [NN * C1T];   // gemm1 out (fp16)
__device__ __align__(256) __half g_hacth[NN * C1T];   // layer2 input (fp16)
__device__ __align__(256) __half g_h2h  [NN * C2T];   // gemm2 out (fp16)
__device__ float g_as1[NN * 4];
__device__ float g_ad1[NN * 4];
__device__ float g_as2[NN];
__device__ float g_ad2[NN];
__device__ int   g_deg[NN];
__device__ int   g_pos[NN];
__device__ int   g_rowptr[NN + 1];
__device__ int   g_srcs[ETOT];
__device__ int   g_bsum[SCAN_BLKS + 1];

// row strides for vectorized gathers
#define H1_U4 (C1T / 8)    // 256 halves / 8 per uint4 = 32
#define H2_U2 (C2T / 4)    // 128 halves / 4 per uint2 = 32

// ---------------- CSR build --------------------------------------------------
__global__ void csr_init(int* __restrict__ deg, int* __restrict__ pos, int N) {
    int i = blockIdx.x * blockDim.x + threadIdx.x;
    if (i < N) { deg[i] = 1; pos[i] = 0; }   // deg starts at 1: self loop
}

__global__ void csr_count(const int* __restrict__ ei, int* __restrict__ deg, int E) {
    int i = blockIdx.x * blockDim.x + threadIdx.x;
    if (i < E) atomicAdd(&deg[ei[E + i]], 1);
}

// ---- scan phase 1: per-block (1024 items) local exclusive scan + block sum --
__global__ __launch_bounds__(256)
void scan1(const int* __restrict__ deg, int* __restrict__ rowptr,
           int* __restrict__ bsum, int N) {
    __shared__ int ts[256];
    int t = threadIdx.x;
    int base = blockIdx.x * SCAN_TILE + t * 4;
    int v[4]; int s = 0;
    #pragma unroll
    for (int q = 0; q < 4; q++) {
        v[q] = (base + q < N) ? deg[base + q] : 0;
        s += v[q];
    }
    ts[t] = s;
    __syncthreads();
    #pragma unroll
    for (int off = 1; off < 256; off <<= 1) {
        int u = (t >= off) ? ts[t - off] : 0;
        __syncthreads();
        ts[t] += u;
        __syncthreads();
    }
    int run = (t == 0) ? 0 : ts[t - 1];
    #pragma unroll
    for (int q = 0; q < 4; q++) {
        if (base + q < N) rowptr[base + q] = run;
        run += v[q];
    }
    if (t == 255) bsum[blockIdx.x] = ts[255];
}

// ---- scan phases 2+3 fused: every block re-scans the block sums in shared --
__global__ __launch_bounds__(256)
void scan23(int* __restrict__ rowptr, const int* __restrict__ bsum, int N) {
    __shared__ int ts[64];
    int t = threadIdx.x;
    if (t < 64) ts[t] = (t < SCAN_BLKS) ? bsum[t] : 0;
    __syncthreads();
    #pragma unroll
    for (int off = 1; off < 64; off <<= 1) {
        int u = (t < 64 && t >= off) ? ts[t - off] : 0;
        __syncthreads();
        if (t < 64) ts[t] += u;
        __syncthreads();
    }
    int i = blockIdx.x * blockDim.x + t;
    if (i < N) {
        int blk = i / SCAN_TILE;
        if (blk > 0) rowptr[i] += ts[blk - 1];
    }
    if (i == N) rowptr[N] = ts[SCAN_BLKS - 1];
}

__global__ void csr_scatter(const int* __restrict__ ei,
                            const int* __restrict__ rowptr, int* __restrict__ pos,
                            int* __restrict__ srcs, int E, int N) {
    int i = blockIdx.x * blockDim.x + threadIdx.x;
    if (i >= E + N) return;
    int src, dst;
    if (i < E) { src = ei[i]; dst = ei[E + i]; }
    else       { src = dst = i - E; }
    int p = atomicAdd(&pos[dst], 1);
    srcs[rowptr[dst] + p] = src;
}

// ---------------- fp16 tensor-core GEMM (m16n8k16) ---------------------------
// C[M,Ncols] = A[M,K] @ B[K,Ncols]; A fp32 or fp16, B fp32, out fp16,
// fp32 accumulate. fp16 mantissa == tf32 mantissa; operands O(0.1-10), so
// precision matches the tf32 version while halving mma count + fragment LDS.
// Smem stores packed half2 along k: As2[k/2][m], Bs2[k/2][n]. The m16n8k16
// f16 fragment pattern == m16n8k8 tf32 pattern with regs holding k-pairs.
__device__ __forceinline__ uint32_t pack_h2(float x, float y) {
    __half2 h = __floats2half2_rn(x, y);
    return *reinterpret_cast<uint32_t*>(&h);
}

__device__ __forceinline__ void mma_f16(float* d, const uint32_t* a, const uint32_t* b) {
    asm volatile(
        "mma.sync.aligned.m16n8k16.row.col.f32.f16.f16.f32 "
        "{%0,%1,%2,%3}, {%4,%5,%6,%7}, {%8,%9}, {%0,%1,%2,%3};"
        : "+f"(d[0]), "+f"(d[1]), "+f"(d[2]), "+f"(d[3])
        : "r"(a[0]), "r"(a[1]), "r"(a[2]), "r"(a[3]), "r"(b[0]), "r"(b[1]));
}

template <int K, typename AT>
__global__ __launch_bounds__(256)
void gemm_f16(const AT* __restrict__ A, const float* __restrict__ B,
              __half* __restrict__ C, int M, int Ncols) {
    __shared__ uint32_t As2[8][132];   // [k/2][m] half2, pad -> conflict-free
    __shared__ uint32_t Bs2[8][132];   // [k/2][n] half2
    int tid  = threadIdx.x;
    int wid  = tid >> 5;
    int lane = tid & 31;
    int row0 = blockIdx.y * 128;
    int col0 = blockIdx.x * 128;
    int m0 = (wid >> 2) * 64;
    int n0 = (wid & 3) * 32;
    int rq = lane >> 2;                // 0..7
    int kl = lane & 3;                 // 0..3

    float acc[4][4][4];
    #pragma unroll
    for (int mt = 0; mt < 4; mt++)
        #pragma unroll
        for (int nt = 0; nt < 4; nt++)
            #pragma unroll
            for (int r = 0; r < 4; r++) acc[mt][nt][r] = 0.f;

    for (int k0 = 0; k0 < K; k0 += 16) {
        // ---- stage A: 128 rows x 16 k -> As2[8][128] ----
        uint32_t a_h2[2][2]; int a_row[2], a_kp[2];   // fp32 path: 2 loads
        uint32_t a_h2f[4];                            // fp16 path: 1 load
        if (sizeof(AT) == 4) {
            #pragma unroll
            for (int u = 0; u < 2; u++) {
                int l = tid + u * 256;
                a_row[u] = l >> 2;
                a_kp[u]  = (l & 3) * 2;              // k-pair index 0,2,4,6
                int gr = row0 + a_row[u];
                float4 v = (gr < M)
                    ? *reinterpret_cast<const float4*>(
                          (const float*)A + (size_t)gr * K + k0 + a_kp[u] * 2)
                    : make_float4(0.f, 0.f, 0.f, 0.f);
                a_h2[u][0] = pack_h2(v.x, v.y);
                a_h2[u][1] = pack_h2(v.z, v.w);
            }
        } else {
            a_row[0] = tid >> 1;
            a_kp[0]  = (tid & 1) * 4;                // k-pair index 0 or 4
            int gr = row0 + a_row[0];
            uint4 v = (gr < M)
                ? *reinterpret_cast<const uint4*>(
                      (const __half*)A + (size_t)gr * K + k0 + a_kp[0] * 2)
                : make_uint4(0u, 0u, 0u, 0u);
            a_h2f[0] = v.x; a_h2f[1] = v.y; a_h2f[2] = v.z; a_h2f[3] = v.w;
        }
        // ---- stage B: 16 k x 128 n; pack k-pairs. thread: kp=tid>>5, nc=tid&31
        int b_kp = tid >> 5;                          // 0..7
        int b_nc = (tid & 31) * 4;
        float4 bv0 = *reinterpret_cast<const float4*>(
            B + (size_t)(k0 + b_kp * 2 + 0) * Ncols + col0 + b_nc);
        float4 bv1 = *reinterpret_cast<const float4*>(
            B + (size_t)(k0 + b_kp * 2 + 1) * Ncols + col0 + b_nc);
        __syncthreads();   // previous tile fully consumed
        if (sizeof(AT) == 4) {
            #pragma unroll
            for (int u = 0; u < 2; u++) {
                As2[a_kp[u] + 0][a_row[u]] = a_h2[u][0];
                As2[a_kp[u] + 1][a_row[u]] = a_h2[u][1];
            }
        } else {
            #pragma unroll
            for (int j = 0; j < 4; j++)
                As2[a_kp[0] + j][a_row[0]] = a_h2f[j];
        }
        {
            uint32_t* bp = &Bs2[b_kp][b_nc];
            bp[0] = pack_h2(bv0.x, bv1.x);
            bp[1] = pack_h2(bv0.y, bv1.y);
            bp[2] = pack_h2(bv0.z, bv1.z);
            bp[3] = pack_h2(bv0.w, bv1.w);
        }
        __syncthreads();

        // ---- one m16n8k16 step covers all 16 k ----
        uint32_t af[4][4], bf[4][2];
        #pragma unroll
        for (int mt = 0; mt < 4; mt++) {
            int r = m0 + mt * 16 + rq;
            af[mt][0] = As2[kl][r];     af[mt][1] = As2[kl][r + 8];
            af[mt][2] = As2[kl + 4][r]; af[mt][3] = As2[kl + 4][r + 8];
        }
        #pragma unroll
        for (int nt = 0; nt < 4; nt++) {
            int c = n0 + nt * 8 + rq;
            bf[nt][0] = Bs2[kl][c];
            bf[nt][1] = Bs2[kl + 4][c];
        }
        #pragma unroll
        for (int mt = 0; mt < 4; mt++)
            #pragma unroll
            for (int nt = 0; nt < 4; nt++)
                mma_f16(acc[mt][nt], af[mt], bf[nt]);
    }

    // epilogue: fp16 output, per-thread half2 fragments
    #pragma unroll
    for (int mt = 0; mt < 4; mt++) {
        int r_lo = row0 + m0 + mt * 16 + rq;
        int r_hi = r_lo + 8;
        #pragma unroll
        for (int nt = 0; nt < 4; nt++) {
            int c = col0 + n0 + nt * 8 + 2 * kl;
            if (r_lo < M)
                *reinterpret_cast<__half2*>(C + (size_t)r_lo * Ncols + c) =
                    __floats2half2_rn(acc[mt][nt][0], acc[mt][nt][1]);
            if (r_hi < M)
                *reinterpret_cast<__half2*>(C + (size_t)r_hi * Ncols + c) =
                    __floats2half2_rn(acc[mt][nt][2], acc[mt][nt][3]);
        }
    }
}

// ---------------- attention coefficients (fp16 features, fp32 math) ---------
__global__ void att_dot(const __half* __restrict__ h,
                        const float* __restrict__ atts,
                        const float* __restrict__ attd,
                        float* __restrict__ as_, float* __restrict__ ad_,
                        int N, int H, int C) {
    int i = blockIdx.x * blockDim.x + threadIdx.x;
    if (i >= N * H) return;
    int hh = i % H;
    const __half2* hp = reinterpret_cast<const __half2*>(h + (size_t)i * C);
    const float* sp = atts + hh * C;
    const float* dp = attd + hh * C;
    float s = 0.f, d = 0.f;
    for (int c = 0; c < C / 2; c++) {
        float2 v = __half22float2(hp[c]);
        s += v.x * sp[2 * c] + v.y * sp[2 * c + 1];
        d += v.x * dp[2 * c] + v.y * dp[2 * c + 1];
    }
    as_[i] = s;
    ad_[i] = d;
}

// ---------------- aggregation helpers ----------------------------------------
__device__ __forceinline__ float lrelu_exp(float e) {
    e = (e > 0.f) ? e : 0.2f * e;
    return __expf(e);                   // softmax shift-invariant: no max pass
}

__device__ __forceinline__ void acc8(float* a, const uint4& hv, float wt) {
    const __half2* hp = reinterpret_cast<const __half2*>(&hv);
    #pragma unroll
    for (int q = 0; q < 4; q++) {
        float2 f = __half22float2(hp[q]);
        a[2 * q]     += wt * f.x;
        a[2 * q + 1] += wt * f.y;
    }
}

__device__ __forceinline__ void acc4(float4& a, const uint2& hv, float wt) {
    float2 f0 = __half22float2(*reinterpret_cast<const __half2*>(&hv.x));
    float2 f1 = __half22float2(*reinterpret_cast<const __half2*>(&hv.y));
    a.x += wt * f0.x; a.y += wt * f0.y; a.z += wt * f1.x; a.w += wt * f1.y;
}

// ---------------- layer1 aggregation: warp per dst node, 4-edge unroll -------
__global__ __launch_bounds__(256)
void agg1(const int* __restrict__ rowptr, const int* __restrict__ srcs,
          const float* __restrict__ as1, const float* __restrict__ ad1,
          const __half* __restrict__ h1, const float* __restrict__ b1,
          __half* __restrict__ hact, int N) {
    int w = (blockIdx.x * blockDim.x + threadIdx.x) >> 5;
    if (w >= N) return;
    int lane = threadIdx.x & 31;
    int head = lane >> 3;
    float adn = ad1[w * 4 + head];
    int beg = rowptr[w], end = rowptr[w + 1];

    const uint4* hb = reinterpret_cast<const uint4*>(h1);
    float a[8] = {0.f, 0.f, 0.f, 0.f, 0.f, 0.f, 0.f, 0.f};
    float den = 0.f;
    int j = beg;
    for (; j + 4 <= end; j += 4) {
        int s0 = srcs[j], s1 = srcs[j + 1], s2 = srcs[j + 2], s3 = srcs[j + 3];
        float e0 = as1[s0 * 4 + head];
        float e1 = as1[s1 * 4 + head];
        float e2 = as1[s2 * 4 + head];
        float e3 = as1[s3 * 4 + head];
        uint4 v0 = hb[(size_t)s0 * H1_U4 + lane];
        uint4 v1 = hb[(size_t)s1 * H1_U4 + lane];
        uint4 v2 = hb[(size_t)s2 * H1_U4 + lane];
        uint4 v3 = hb[(size_t)s3 * H1_U4 + lane];
        float w0 = lrelu_exp(e0 + adn);
        float w1 = lrelu_exp(e1 + adn);
        float w2 = lrelu_exp(e2 + adn);
        float w3 = lrelu_exp(e3 + adn);
        den += (w0 + w1) + (w2 + w3);
        acc8(a, v0, w0); acc8(a, v1, w1); acc8(a, v2, w2); acc8(a, v3, w3);
    }
    for (; j < end; j++) {
        int s = srcs[j];
        float wt = lrelu_exp(as1[s * 4 + head] + adn);
        den += wt;
        uint4 v = hb[(size_t)s * H1_U4 + lane];
        acc8(a, v, wt);
    }
    float inv = 1.f / (den + 1e-16f);
    int c = lane * 8;
    __half2 o[4];
    #pragma unroll
    for (int q = 0; q < 4; q++) {
        float ox = fmaxf(a[2 * q]     * inv + b1[c + 2 * q],     0.f);
        float oy = fmaxf(a[2 * q + 1] * inv + b1[c + 2 * q + 1], 0.f);
        o[q] = __floats2half2_rn(ox, oy);
    }
    reinterpret_cast<uint4*>(hact + (size_t)w * C1T)[lane] =
        *reinterpret_cast<const uint4*>(o);
}

// ---------------- layer2 aggregation: warp per dst node, 4-edge unroll -------
__global__ __launch_bounds__(256)
void agg2(const int* __restrict__ rowptr, const int* __restrict__ srcs,
          const float* __restrict__ as2, const float* __restrict__ ad2,
          const __half* __restrict__ h2, const float* __restrict__ b2,
          float* __restrict__ out, int N) {
    int w = (blockIdx.x * blockDim.x + threadIdx.x) >> 5;
    if (w >= N) return;
    int lane = threadIdx.x & 31;
    float adn = ad2[w];
    int beg = rowptr[w], end = rowptr[w + 1];

    const uint2* hb = reinterpret_cast<const uint2*>(h2);
    float4 a = make_float4(0.f, 0.f, 0.f, 0.f);
    float den = 0.f;
    int j = beg;
    for (; j + 4 <= end; j += 4) {
        int s0 = srcs[j], s1 = srcs[j + 1], s2 = srcs[j + 2], s3 = srcs[j + 3];
        float e0 = as2[s0], e1 = as2[s1], e2 = as2[s2], e3 = as2[s3];
        uint2 v0 = hb[(size_t)s0 * H2_U2 + lane];
        uint2 v1 = hb[(size_t)s1 * H2_U2 + lane];
        uint2 v2 = hb[(size_t)s2 * H2_U2 + lane];
        uint2 v3 = hb[(size_t)s3 * H2_U2 + lane];
        float w0 = lrelu_exp(e0 + adn);
        float w1 = lrelu_exp(e1 + adn);
        float w2 = lrelu_exp(e2 + adn);
        float w3 = lrelu_exp(e3 + adn);
        den += (w0 + w1) + (w2 + w3);
        acc4(a, v0, w0); acc4(a, v1, w1); acc4(a, v2, w2); acc4(a, v3, w3);
    }
    for (; j < end; j++) {
        int s = srcs[j];
        float wt = lrelu_exp(as2[s] + adn);
        den += wt;
        uint2 v = hb[(size_t)s * H2_U2 + lane];
        acc4(a, v, wt);
    }
    float inv = 1.f / (den + 1e-16f);
    int c = lane * 4;
    float4 bb = *reinterpret_cast<const float4*>(b2 + c);
    float4 o = make_float4(fmaxf(a.x * inv + bb.x, 0.f),
                           fmaxf(a.y * inv + bb.y, 0.f),
                           fmaxf(a.z * inv + bb.z, 0.f),
                           fmaxf(a.w * inv + bb.w, 0.f));
    reinterpret_cast<float4*>(out + (size_t)w * C2T)[lane] = o;
}

// ---------------- launch -----------------------------------------------------
template <typename T, size_t S>
static T* sym_addr(T (&sym)[S]) {
    void* p = nullptr;
    cudaGetSymbolAddress(&p, sym);   // host API, capture-safe
    return (T*)p;
}

// Side stream + fork/join events. Created on FIRST call (the uncaptured
// correctness run), persisted across calls: destroying a stream that
// participates in an active capture would invalidate the capture.
struct StreamCtx {
    cudaStream_t s2;
    cudaEvent_t fork, join;
    StreamCtx() {
        cudaStreamCreateWithFlags(&s2, cudaStreamNonBlocking);
        cudaEventCreateWithFlags(&fork, cudaEventDisableTiming);
        cudaEventCreateWithFlags(&join, cudaEventDisableTiming);
    }
};

extern "C" void kernel_launch(void* const* d_in, const int* in_sizes, int n_in,
                              void* d_out, int out_size) {
    static StreamCtx ctx;   // constructed on first (correctness) call

    const float* x        = (const float*)d_in[0];
    const int*   ei       = (const int*)  d_in[1];
    const float* W1       = (const float*)d_in[2];
    const float* att_src1 = (const float*)d_in[3];
    const float* att_dst1 = (const float*)d_in[4];
    const float* b1       = (const float*)d_in[5];
    const float* W2       = (const float*)d_in[6];
    const float* att_src2 = (const float*)d_in[7];
    const float* att_dst2 = (const float*)d_in[8];
    const float* b2       = (const float*)d_in[9];
    float* out = (float*)d_out;

    __half* h1h   = sym_addr(g_h1h);
    __half* hacth = sym_addr(g_hacth);
    __half* h2h   = sym_addr(g_h2h);
    float* as1  = sym_addr(g_as1);
    float* ad1  = sym_addr(g_ad1);
    float* as2  = sym_addr(g_as2);
    float* ad2  = sym_addr(g_ad2);
    int* deg    = sym_addr(g_deg);
    int* pos    = sym_addr(g_pos);
    int* rowptr = sym_addr(g_rowptr);
    int* srcs   = sym_addr(g_srcs);
    int* bsum   = sym_addr(g_bsum);

    int N = in_sizes[0] / EIN;   // 50000
    int E = in_sizes[1] / 2;     // 800000
    int Etot = E + N;

    // ---- fork: CSR build (independent of gemm1/att_dot1) on side stream ----
    cudaEventRecord(ctx.fork, 0);
    cudaStreamWaitEvent(ctx.s2, ctx.fork, 0);

    csr_init   <<<(N + 255) / 256, 256, 0, ctx.s2>>>(deg, pos, N);
    csr_count  <<<(E + 255) / 256, 256, 0, ctx.s2>>>(ei, deg, E);
    scan1      <<<SCAN_BLKS, 256, 0, ctx.s2>>>(deg, rowptr, bsum, N);
    scan23     <<<(N + 256) / 256, 256, 0, ctx.s2>>>(rowptr, bsum, N);
    csr_scatter<<<(Etot + 255) / 256, 256, 0, ctx.s2>>>(ei, rowptr, pos, srcs, E, N);
    cudaEventRecord(ctx.join, ctx.s2);

    // ---- main stream: layer-1 linear + attention coefficients (overlapped) --
    {
        dim3 grid(C1T / 128, (N + 127) / 128);
        gemm_f16<EIN, float><<<grid, 256>>>(x, W1, h1h, N, C1T);
    }
    att_dot<<<(N * 4 + 255) / 256, 256>>>(h1h, att_src1, att_dst1, as1, ad1, N, 4, 64);

    // ---- join: agg1 needs BOTH the CSR and the attention coefficients ------
    cudaStreamWaitEvent(0, ctx.join, 0);
    agg1<<<((size_t)N * 32 + 255) / 256, 256>>>(rowptr, srcs, as1, ad1, h1h, b1, hacth, N);

    // ---- layer 2 ----
    {
        dim3 grid(C2T / 128, (N + 127) / 128);
        gemm_f16<C1T, __half><<<grid, 256>>>(hacth, W2, h2h, N, C2T);
    }
    att_dot<<<(N + 255) / 256, 256>>>(h2h, att_src2, att_dst2, as2, ad2, N, 1, 128);
    agg2<<<((size_t)N * 32 + 255) / 256, 256>>>(rowptr, srcs, as2, ad2, h2h, b2, out, N);
}

// round 17
// speedup vs baseline: 2.9452x; 1.0177x over previous
#include <cuda_runtime.h>
#include <cuda_fp16.h>
#include <cstdint>

#define NN   50000
#define EIN  128
#define C1T  256   // H1*C1
#define C2T  128   // H2*C2
#define EMAX 800000
#define ETOT (EMAX + NN)
#define SCAN_TILE 1024
#define SCAN_BLKS ((NN + SCAN_TILE - 1) / SCAN_TILE)

// ---------------- scratch (device globals; allocation is forbidden) ----------
// Only touched through cudaGetSymbolAddress pointers (host-shadow + ATS trap).
__device__ __align__(256) __half g_h1h  [NN * C1T];   // gemm1 out (fp16)
__device__ __align__(256) __half g_hacth[NN * C1T];   // layer2 input (fp16)
__device__ __align__(256) __half g_h2h  [NN * C2T];   // gemm2 out (fp16)
__device__ float g_as1[NN * 4];
__device__ float g_ad1[NN * 4];
__device__ float g_as2[NN];
__device__ float g_ad2[NN];
__device__ int   g_deg[NN];
__device__ int   g_pos[NN];
__device__ int   g_rowptr[NN + 1];
__device__ int   g_srcs[ETOT];
__device__ int   g_bsum[SCAN_BLKS + 1];

// row strides for vectorized gathers
#define H1_U4 (C1T / 8)    // 256 halves / 8 per uint4 = 32
#define H2_U2 (C2T / 4)    // 128 halves / 4 per uint2 = 32

// ---------------- CSR build --------------------------------------------------
__global__ void csr_init(int* __restrict__ deg, int* __restrict__ pos, int N) {
    int i = blockIdx.x * blockDim.x + threadIdx.x;
    if (i < N) { deg[i] = 1; pos[i] = 0; }   // deg starts at 1: self loop
}

__global__ void csr_count(const int* __restrict__ ei, int* __restrict__ deg, int E) {
    int i = blockIdx.x * blockDim.x + threadIdx.x;
    if (i < E) atomicAdd(&deg[ei[E + i]], 1);
}

// ---- scan phase 1: per-block (1024 items) local exclusive scan + block sum --
__global__ __launch_bounds__(256)
void scan1(const int* __restrict__ deg, int* __restrict__ rowptr,
           int* __restrict__ bsum, int N) {
    __shared__ int ts[256];
    int t = threadIdx.x;
    int base = blockIdx.x * SCAN_TILE + t * 4;
    int v[4]; int s = 0;
    #pragma unroll
    for (int q = 0; q < 4; q++) {
        v[q] = (base + q < N) ? deg[base + q] : 0;
        s += v[q];
    }
    ts[t] = s;
    __syncthreads();
    #pragma unroll
    for (int off = 1; off < 256; off <<= 1) {
        int u = (t >= off) ? ts[t - off] : 0;
        __syncthreads();
        ts[t] += u;
        __syncthreads();
    }
    int run = (t == 0) ? 0 : ts[t - 1];
    #pragma unroll
    for (int q = 0; q < 4; q++) {
        if (base + q < N) rowptr[base + q] = run;
        run += v[q];
    }
    if (t == 255) bsum[blockIdx.x] = ts[255];
}

// ---- scan phases 2+3 fused: every block re-scans the block sums in shared --
__global__ __launch_bounds__(256)
void scan23(int* __restrict__ rowptr, const int* __restrict__ bsum, int N) {
    __shared__ int ts[64];
    int t = threadIdx.x;
    if (t < 64) ts[t] = (t < SCAN_BLKS) ? bsum[t] : 0;
    __syncthreads();
    #pragma unroll
    for (int off = 1; off < 64; off <<= 1) {
        int u = (t < 64 && t >= off) ? ts[t - off] : 0;
        __syncthreads();
        if (t < 64) ts[t] += u;
        __syncthreads();
    }
    int i = blockIdx.x * blockDim.x + t;
    if (i < N) {
        int blk = i / SCAN_TILE;
        if (blk > 0) rowptr[i] += ts[blk - 1];
    }
    if (i == N) rowptr[N] = ts[SCAN_BLKS - 1];
}

__global__ void csr_scatter(const int* __restrict__ ei,
                            const int* __restrict__ rowptr, int* __restrict__ pos,
                            int* __restrict__ srcs, int E, int N) {
    int i = blockIdx.x * blockDim.x + threadIdx.x;
    if (i >= E + N) return;
    int src, dst;
    if (i < E) { src = ei[i]; dst = ei[E + i]; }
    else       { src = dst = i - E; }
    int p = atomicAdd(&pos[dst], 1);
    srcs[rowptr[dst] + p] = src;
}

// ---------------- fp16 tensor-core GEMM (m16n8k16), software-pipelined -------
// C[M,Ncols] = A[M,K] @ B[K,Ncols]; A fp32 or fp16, B fp32, out fp16,
// fp32 accumulate. Next k-tile's gmem loads are issued BEFORE the current
// tile's mmas so load latency hides under tensor work (R16: single-stage
// loop exposed full gmem latency per iteration after mma count halved).
__device__ __forceinline__ uint32_t pack_h2(float x, float y) {
    __half2 h = __floats2half2_rn(x, y);
    return *reinterpret_cast<uint32_t*>(&h);
}

__device__ __forceinline__ void mma_f16(float* d, const uint32_t* a, const uint32_t* b) {
    asm volatile(
        "mma.sync.aligned.m16n8k16.row.col.f32.f16.f16.f32 "
        "{%0,%1,%2,%3}, {%4,%5,%6,%7}, {%8,%9}, {%0,%1,%2,%3};"
        : "+f"(d[0]), "+f"(d[1]), "+f"(d[2]), "+f"(d[3])
        : "r"(a[0]), "r"(a[1]), "r"(a[2]), "r"(a[3]), "r"(b[0]), "r"(b[1]));
}

template <int K, typename AT>
__global__ __launch_bounds__(256)
void gemm_f16(const AT* __restrict__ A, const float* __restrict__ B,
              __half* __restrict__ C, int M, int Ncols) {
    __shared__ uint32_t As2[8][132];   // [k/2][m] half2, pad -> conflict-free
    __shared__ uint32_t Bs2[8][132];   // [k/2][n] half2
    int tid  = threadIdx.x;
    int wid  = tid >> 5;
    int lane = tid & 31;
    int row0 = blockIdx.y * 128;
    int col0 = blockIdx.x * 128;
    int m0 = (wid >> 2) * 64;
    int n0 = (wid & 3) * 32;
    int rq = lane >> 2;                // 0..7
    int kl = lane & 3;                 // 0..3

    // loop-invariant staging indices
    int a_row[2], a_kp[2];
    if (sizeof(AT) == 4) {
        #pragma unroll
        for (int u = 0; u < 2; u++) {
            int l = tid + u * 256;
            a_row[u] = l >> 2;
            a_kp[u]  = (l & 3) * 2;              // k-pair index 0,2,4,6
        }
    } else {
        a_row[0] = tid >> 1;
        a_kp[0]  = (tid & 1) * 4;                // k-pair index 0 or 4
    }
    int b_kp = tid >> 5;                          // 0..7
    int b_nc = (tid & 31) * 4;

    // staging registers (live across the mma section -> loads overlap mma)
    float4 av[2]; uint4 avh;
    float4 bv0, bv1;

    auto load_tile = [&](int k0) {
        if (sizeof(AT) == 4) {
            #pragma unroll
            for (int u = 0; u < 2; u++) {
                int gr = row0 + a_row[u];
                av[u] = (gr < M)
                    ? *reinterpret_cast<const float4*>(
                          (const float*)A + (size_t)gr * K + k0 + a_kp[u] * 2)
                    : make_float4(0.f, 0.f, 0.f, 0.f);
            }
        } else {
            int gr = row0 + a_row[0];
            avh = (gr < M)
                ? *reinterpret_cast<const uint4*>(
                      (const __half*)A + (size_t)gr * K + k0 + a_kp[0] * 2)
                : make_uint4(0u, 0u, 0u, 0u);
        }
        bv0 = *reinterpret_cast<const float4*>(
            B + (size_t)(k0 + b_kp * 2 + 0) * Ncols + col0 + b_nc);
        bv1 = *reinterpret_cast<const float4*>(
            B + (size_t)(k0 + b_kp * 2 + 1) * Ncols + col0 + b_nc);
    };

    float acc[4][4][4];
    #pragma unroll
    for (int mt = 0; mt < 4; mt++)
        #pragma unroll
        for (int nt = 0; nt < 4; nt++)
            #pragma unroll
            for (int r = 0; r < 4; r++) acc[mt][nt][r] = 0.f;

    load_tile(0);   // prologue

    for (int k0 = 0; k0 < K; k0 += 16) {
        __syncthreads();   // previous tile's mmas done -> smem free
        // store staged regs -> smem (with fp32->fp16 pack where needed)
        if (sizeof(AT) == 4) {
            #pragma unroll
            for (int u = 0; u < 2; u++) {
                As2[a_kp[u] + 0][a_row[u]] = pack_h2(av[u].x, av[u].y);
                As2[a_kp[u] + 1][a_row[u]] = pack_h2(av[u].z, av[u].w);
            }
        } else {
            As2[a_kp[0] + 0][a_row[0]] = avh.x;
            As2[a_kp[0] + 1][a_row[0]] = avh.y;
            As2[a_kp[0] + 2][a_row[0]] = avh.z;
            As2[a_kp[0] + 3][a_row[0]] = avh.w;
        }
        {
            uint32_t* bp = &Bs2[b_kp][b_nc];
            bp[0] = pack_h2(bv0.x, bv1.x);
            bp[1] = pack_h2(bv0.y, bv1.y);
            bp[2] = pack_h2(bv0.z, bv1.z);
            bp[3] = pack_h2(bv0.w, bv1.w);
        }
        __syncthreads();

        // prefetch NEXT tile while this tile's mmas run
        if (k0 + 16 < K) load_tile(k0 + 16);

        // ---- one m16n8k16 step covers all 16 k ----
        uint32_t af[4][4], bf[4][2];
        #pragma unroll
        for (int mt = 0; mt < 4; mt++) {
            int r = m0 + mt * 16 + rq;
            af[mt][0] = As2[kl][r];     af[mt][1] = As2[kl][r + 8];
            af[mt][2] = As2[kl + 4][r]; af[mt][3] = As2[kl + 4][r + 8];
        }
        #pragma unroll
        for (int nt = 0; nt < 4; nt++) {
            int c = n0 + nt * 8 + rq;
            bf[nt][0] = Bs2[kl][c];
            bf[nt][1] = Bs2[kl + 4][c];
        }
        #pragma unroll
        for (int mt = 0; mt < 4; mt++)
            #pragma unroll
            for (int nt = 0; nt < 4; nt++)
                mma_f16(acc[mt][nt], af[mt], bf[nt]);
    }

    // epilogue: fp16 output, per-thread half2 fragments
    #pragma unroll
    for (int mt = 0; mt < 4; mt++) {
        int r_lo = row0 + m0 + mt * 16 + rq;
        int r_hi = r_lo + 8;
        #pragma unroll
        for (int nt = 0; nt < 4; nt++) {
            int c = col0 + n0 + nt * 8 + 2 * kl;
            if (r_lo < M)
                *reinterpret_cast<__half2*>(C + (size_t)r_lo * Ncols + c) =
                    __floats2half2_rn(acc[mt][nt][0], acc[mt][nt][1]);
            if (r_hi < M)
                *reinterpret_cast<__half2*>(C + (size_t)r_hi * Ncols + c) =
                    __floats2half2_rn(acc[mt][nt][2], acc[mt][nt][3]);
        }
    }
}

// ---------------- attention coefficients (fp16 features, fp32 math) ---------
__global__ void att_dot(const __half* __restrict__ h,
                        const float* __restrict__ atts,
                        const float* __restrict__ attd,
                        float* __restrict__ as_, float* __restrict__ ad_,
                        int N, int H, int C) {
    int i = blockIdx.x * blockDim.x + threadIdx.x;
    if (i >= N * H) return;
    int hh = i % H;
    const __half2* hp = reinterpret_cast<const __half2*>(h + (size_t)i * C);
    const float* sp = atts + hh * C;
    const float* dp = attd + hh * C;
    float s = 0.f, d = 0.f;
    for (int c = 0; c < C / 2; c++) {
        float2 v = __half22float2(hp[c]);
        s += v.x * sp[2 * c] + v.y * sp[2 * c + 1];
        d += v.x * dp[2 * c] + v.y * dp[2 * c + 1];
    }
    as_[i] = s;
    ad_[i] = d;
}

// ---------------- aggregation helpers ----------------------------------------
__device__ __forceinline__ float lrelu_exp(float e) {
    e = (e > 0.f) ? e : 0.2f * e;
    return __expf(e);                   // softmax shift-invariant: no max pass
}

__device__ __forceinline__ void acc8(float* a, const uint4& hv, float wt) {
    const __half2* hp = reinterpret_cast<const __half2*>(&hv);
    #pragma unroll
    for (int q = 0; q < 4; q++) {
        float2 f = __half22float2(hp[q]);
        a[2 * q]     += wt * f.x;
        a[2 * q + 1] += wt * f.y;
    }
}

__device__ __forceinline__ void acc4(float4& a, const uint2& hv, float wt) {
    float2 f0 = __half22float2(*reinterpret_cast<const __half2*>(&hv.x));
    float2 f1 = __half22float2(*reinterpret_cast<const __half2*>(&hv.y));
    a.x += wt * f0.x; a.y += wt * f0.y; a.z += wt * f1.x; a.w += wt * f1.y;
}

// ---------------- layer1 aggregation: warp per dst node, 4-edge unroll -------
__global__ __launch_bounds__(256)
void agg1(const int* __restrict__ rowptr, const int* __restrict__ srcs,
          const float* __restrict__ as1, const float* __restrict__ ad1,
          const __half* __restrict__ h1, const float* __restrict__ b1,
          __half* __restrict__ hact, int N) {
    int w = (blockIdx.x * blockDim.x + threadIdx.x) >> 5;
    if (w >= N) return;
    int lane = threadIdx.x & 31;
    int head = lane >> 3;
    float adn = ad1[w * 4 + head];
    int beg = rowptr[w], end = rowptr[w + 1];

    const uint4* hb = reinterpret_cast<const uint4*>(h1);
    float a[8] = {0.f, 0.f, 0.f, 0.f, 0.f, 0.f, 0.f, 0.f};
    float den = 0.f;
    int j = beg;
    for (; j + 4 <= end; j += 4) {
        int s0 = srcs[j], s1 = srcs[j + 1], s2 = srcs[j + 2], s3 = srcs[j + 3];
        float e0 = as1[s0 * 4 + head];
        float e1 = as1[s1 * 4 + head];
        float e2 = as1[s2 * 4 + head];
        float e3 = as1[s3 * 4 + head];
        uint4 v0 = hb[(size_t)s0 * H1_U4 + lane];
        uint4 v1 = hb[(size_t)s1 * H1_U4 + lane];
        uint4 v2 = hb[(size_t)s2 * H1_U4 + lane];
        uint4 v3 = hb[(size_t)s3 * H1_U4 + lane];
        float w0 = lrelu_exp(e0 + adn);
        float w1 = lrelu_exp(e1 + adn);
        float w2 = lrelu_exp(e2 + adn);
        float w3 = lrelu_exp(e3 + adn);
        den += (w0 + w1) + (w2 + w3);
        acc8(a, v0, w0); acc8(a, v1, w1); acc8(a, v2, w2); acc8(a, v3, w3);
    }
    for (; j < end; j++) {
        int s = srcs[j];
        float wt = lrelu_exp(as1[s * 4 + head] + adn);
        den += wt;
        uint4 v = hb[(size_t)s * H1_U4 + lane];
        acc8(a, v, wt);
    }
    float inv = 1.f / (den + 1e-16f);
    int c = lane * 8;
    __half2 o[4];
    #pragma unroll
    for (int q = 0; q < 4; q++) {
        float ox = fmaxf(a[2 * q]     * inv + b1[c + 2 * q],     0.f);
        float oy = fmaxf(a[2 * q + 1] * inv + b1[c + 2 * q + 1], 0.f);
        o[q] = __floats2half2_rn(ox, oy);
    }
    reinterpret_cast<uint4*>(hact + (size_t)w * C1T)[lane] =
        *reinterpret_cast<const uint4*>(o);
}

// ---------------- layer2 aggregation: warp per dst node, 4-edge unroll -------
__global__ __launch_bounds__(256)
void agg2(const int* __restrict__ rowptr, const int* __restrict__ srcs,
          const float* __restrict__ as2, const float* __restrict__ ad2,
          const __half* __restrict__ h2, const float* __restrict__ b2,
          float* __restrict__ out, int N) {
    int w = (blockIdx.x * blockDim.x + threadIdx.x) >> 5;
    if (w >= N) return;
    int lane = threadIdx.x & 31;
    float adn = ad2[w];
    int beg = rowptr[w], end = rowptr[w + 1];

    const uint2* hb = reinterpret_cast<const uint2*>(h2);
    float4 a = make_float4(0.f, 0.f, 0.f, 0.f);
    float den = 0.f;
    int j = beg;
    for (; j + 4 <= end; j += 4) {
        int s0 = srcs[j], s1 = srcs[j + 1], s2 = srcs[j + 2], s3 = srcs[j + 3];
        float e0 = as2[s0], e1 = as2[s1], e2 = as2[s2], e3 = as2[s3];
        uint2 v0 = hb[(size_t)s0 * H2_U2 + lane];
        uint2 v1 = hb[(size_t)s1 * H2_U2 + lane];
        uint2 v2 = hb[(size_t)s2 * H2_U2 + lane];
        uint2 v3 = hb[(size_t)s3 * H2_U2 + lane];
        float w0 = lrelu_exp(e0 + adn);
        float w1 = lrelu_exp(e1 + adn);
        float w2 = lrelu_exp(e2 + adn);
        float w3 = lrelu_exp(e3 + adn);
        den += (w0 + w1) + (w2 + w3);
        acc4(a, v0, w0); acc4(a, v1, w1); acc4(a, v2, w2); acc4(a, v3, w3);
    }
    for (; j < end; j++) {
        int s = srcs[j];
        float wt = lrelu_exp(as2[s] + adn);
        den += wt;
        uint2 v = hb[(size_t)s * H2_U2 + lane];
        acc4(a, v, wt);
    }
    float inv = 1.f / (den + 1e-16f);
    int c = lane * 4;
    float4 bb = *reinterpret_cast<const float4*>(b2 + c);
    float4 o = make_float4(fmaxf(a.x * inv + bb.x, 0.f),
                           fmaxf(a.y * inv + bb.y, 0.f),
                           fmaxf(a.z * inv + bb.z, 0.f),
                           fmaxf(a.w * inv + bb.w, 0.f));
    reinterpret_cast<float4*>(out + (size_t)w * C2T)[lane] = o;
}

// ---------------- launch -----------------------------------------------------
template <typename T, size_t S>
static T* sym_addr(T (&sym)[S]) {
    void* p = nullptr;
    cudaGetSymbolAddress(&p, sym);   // host API, capture-safe
    return (T*)p;
}

// Side stream + fork/join events. Created on FIRST call (the uncaptured
// correctness run), persisted across calls: destroying a stream that
// participates in an active capture would invalidate the capture.
struct StreamCtx {
    cudaStream_t s2;
    cudaEvent_t fork, join;
    StreamCtx() {
        cudaStreamCreateWithFlags(&s2, cudaStreamNonBlocking);
        cudaEventCreateWithFlags(&fork, cudaEventDisableTiming);
        cudaEventCreateWithFlags(&join, cudaEventDisableTiming);
    }
};

extern "C" void kernel_launch(void* const* d_in, const int* in_sizes, int n_in,
                              void* d_out, int out_size) {
    static StreamCtx ctx;   // constructed on first (correctness) call

    const float* x        = (const float*)d_in[0];
    const int*   ei       = (const int*)  d_in[1];
    const float* W1       = (const float*)d_in[2];
    const float* att_src1 = (const float*)d_in[3];
    const float* att_dst1 = (const float*)d_in[4];
    const float* b1       = (const float*)d_in[5];
    const float* W2       = (const float*)d_in[6];
    const float* att_src2 = (const float*)d_in[7];
    const float* att_dst2 = (const float*)d_in[8];
    const float* b2       = (const float*)d_in[9];
    float* out = (float*)d_out;

    __half* h1h   = sym_addr(g_h1h);
    __half* hacth = sym_addr(g_hacth);
    __half* h2h   = sym_addr(g_h2h);
    float* as1  = sym_addr(g_as1);
    float* ad1  = sym_addr(g_ad1);
    float* as2  = sym_addr(g_as2);
    float* ad2  = sym_addr(g_ad2);
    int* deg    = sym_addr(g_deg);
    int* pos    = sym_addr(g_pos);
    int* rowptr = sym_addr(g_rowptr);
    int* srcs   = sym_addr(g_srcs);
    int* bsum   = sym_addr(g_bsum);

    int N = in_sizes[0] / EIN;   // 50000
    int E = in_sizes[1] / 2;     // 800000
    int Etot = E + N;

    // ---- fork: CSR build (independent of gemm1/att_dot1) on side stream ----
    cudaEventRecord(ctx.fork, 0);
    cudaStreamWaitEvent(ctx.s2, ctx.fork, 0);

    csr_init   <<<(N + 255) / 256, 256, 0, ctx.s2>>>(deg, pos, N);
    csr_count  <<<(E + 255) / 256, 256, 0, ctx.s2>>>(ei, deg, E);
    scan1      <<<SCAN_BLKS, 256, 0, ctx.s2>>>(deg, rowptr, bsum, N);
    scan23     <<<(N + 256) / 256, 256, 0, ctx.s2>>>(rowptr, bsum, N);
    csr_scatter<<<(Etot + 255) / 256, 256, 0, ctx.s2>>>(ei, rowptr, pos, srcs, E, N);
    cudaEventRecord(ctx.join, ctx.s2);

    // ---- main stream: layer-1 linear + attention coefficients (overlapped) --
    {
        dim3 grid(C1T / 128, (N + 127) / 128);
        gemm_f16<EIN, float><<<grid, 256>>>(x, W1, h1h, N, C1T);
    }
    att_dot<<<(N * 4 + 255) / 256, 256>>>(h1h, att_src1, att_dst1, as1, ad1, N, 4, 64);

    // ---- join: agg1 needs BOTH the CSR and the attention coefficients ------
    cudaStreamWaitEvent(0, ctx.join, 0);
    agg1<<<((size_t)N * 32 + 255) / 256, 256>>>(rowptr, srcs, as1, ad1, h1h, b1, hacth, N);

    // ---- layer 2 ----
    {
        dim3 grid(C2T / 128, (N + 127) / 128);
        gemm_f16<C1T, __half><<<grid, 256>>>(hacth, W2, h2h, N, C2T);
    }
    att_dot<<<(N + 255) / 256, 256>>>(h2h, att_src2, att_dst2, as2, ad2, N, 1, 128);
    agg2<<<((size_t)N * 32 + 255) / 256, 256>>>(rowptr, srcs, as2, ad2, h2h, b2, out, N);
}